// round 5
// baseline (speedup 1.0000x reference)
#include <cuda_runtime.h>
#include <cuda_bf16.h>
#include <math.h>
#include <stdint.h>

#define D_MODEL 1024
#define NUM_HEADS 16
#define SEQ 2048
#define BATCH 4
#define D_K 64
#define MTOT (BATCH * SEQ)   // 8192

// Scratch (static device globals; no runtime allocation allowed)
__device__ float g_q[MTOT * D_MODEL];
__device__ float g_k[MTOT * D_MODEL];
__device__ float g_v[MTOT * D_MODEL];
__device__ float g_o[MTOT * D_MODEL];

// ---------------------------------------------------------------------------
// helpers
// ---------------------------------------------------------------------------
__device__ __forceinline__ uint32_t f2tf32(float f) {
    uint32_t r;
    asm("cvt.rna.tf32.f32 %0, %1;" : "=r"(r) : "f"(f));
    return r;
}

__device__ __forceinline__ void mma_tf32(float c[4], uint32_t a0, uint32_t a1,
                                         uint32_t a2, uint32_t a3,
                                         uint32_t b0, uint32_t b1) {
    asm volatile(
        "mma.sync.aligned.m16n8k8.row.col.f32.tf32.tf32.f32 "
        "{%0,%1,%2,%3},{%4,%5,%6,%7},{%8,%9},{%0,%1,%2,%3};"
        : "+f"(c[0]), "+f"(c[1]), "+f"(c[2]), "+f"(c[3])
        : "r"(a0), "r"(a1), "r"(a2), "r"(a3), "r"(b0), "r"(b1));
}

// ---------------------------------------------------------------------------
// tf32 tensor-core GEMM, NT form: C[m,n] = sum_k A[m,k]*B[n,k]
// Block tile 128x128, BK=16, double-buffered FRAGMENT-MAJOR smem:
//   A atom (m16 x k8) -> 32 lanes x 4 regs (512B): one LDS128 per fragment.
//   B atom (n8  x k8) -> 32 lanes x 2 regs (256B): one LDS64  per fragment.
// 256 threads = 8 warps (2x4), warp tile 64x32.
// rope != 0: RoPE on (even,odd) pairs per 64-wide head slice.
// ---------------------------------------------------------------------------
__global__ __launch_bounds__(256)
void gemm_tf32(const float* __restrict__ A, const float* __restrict__ B,
               float* __restrict__ C, int rope, const int* __restrict__ pos)
{
    // A: 8 m-atoms x 2 k-atoms x 128 words = 2048 words (8KB) per stage
    // B: 16 n-atoms x 2 k-atoms x 64 words = 2048 words (8KB) per stage
    __shared__ __align__(16) uint32_t As[2][2048];
    __shared__ __align__(16) uint32_t Bs[2][2048];

    const int tid = threadIdx.x;
    const int warp = tid >> 5;
    const int lane = tid & 31;
    const int gid = lane >> 2;       // 0..7
    const int tig = lane & 3;        // 0..3
    const int warp_m = warp >> 2;    // 0..1
    const int warp_n = warp & 3;     // 0..3

    const int bm = blockIdx.y * 128;
    const int bn = blockIdx.x * 128;

    // loader geometry: thread owns row r, 8 consecutive k at k0
    const int r = tid >> 1;                  // 0..127
    const int k0 = (tid & 1) * 8;            // 0 or 8
    const int kh = k0 >> 3;                  // 0 or 1 (k-atom index)

    // STS bases (word offsets), v-dependent part is compile-time constant
    const int base_a = ((r >> 4) * 2 + kh) * 128 + (r & 7) * 16 + ((r >> 3) & 1);
    const int base_b = ((r >> 3) * 2 + kh) * 64 + (r & 7) * 8;

    float acc[4][4][4];
#pragma unroll
    for (int i = 0; i < 4; i++)
#pragma unroll
        for (int j = 0; j < 4; j++)
#pragma unroll
            for (int v = 0; v < 4; v++) acc[i][j][v] = 0.0f;

    const float* Arow = A + (size_t)(bm + r) * D_MODEL + k0;
    const float* Brow = B + (size_t)(bn + r) * D_MODEL + k0;

    float4 ra0, ra1, rb0, rb1;
    ra0 = *(const float4*)&Arow[0];
    ra1 = *(const float4*)&Arow[4];
    rb0 = *(const float4*)&Brow[0];
    rb1 = *(const float4*)&Brow[4];

    const int NKT = D_MODEL / 16;   // 64
    for (int kt = 0; kt < NKT; kt++) {
        const int cur = kt & 1;
        // STS with tf32 convert into fragment-major layout
        {
            uint32_t* sA = &As[cur][0];
            uint32_t* sB = &Bs[cur][0];
            float va[8] = {ra0.x, ra0.y, ra0.z, ra0.w, ra1.x, ra1.y, ra1.z, ra1.w};
            float vb[8] = {rb0.x, rb0.y, rb0.z, rb0.w, rb1.x, rb1.y, rb1.z, rb1.w};
#pragma unroll
            for (int v = 0; v < 8; v++) {
                sA[base_a + (v & 3) * 4 + (v >> 2) * 2] = f2tf32(va[v]);
                sB[base_b + (v & 3) * 2 + (v >> 2)] = f2tf32(vb[v]);
            }
        }
        __syncthreads();

        if (kt + 1 < NKT) {
            const float* An = Arow + (kt + 1) * 16;
            const float* Bn = Brow + (kt + 1) * 16;
            ra0 = *(const float4*)&An[0];
            ra1 = *(const float4*)&An[4];
            rb0 = *(const float4*)&Bn[0];
            rb1 = *(const float4*)&Bn[4];
        }

        const uint32_t* sA = &As[cur][0];
        const uint32_t* sB = &Bs[cur][0];
        const int lfrag = (gid * 4 + tig);
#pragma unroll
        for (int ks = 0; ks < 2; ks++) {
            uint32_t af[4][4], bf[4][2];
#pragma unroll
            for (int mt = 0; mt < 4; mt++) {
                uint4 t = *(const uint4*)&sA[((warp_m * 4 + mt) * 2 + ks) * 128 + lfrag * 4];
                af[mt][0] = t.x; af[mt][1] = t.y; af[mt][2] = t.z; af[mt][3] = t.w;
            }
#pragma unroll
            for (int nt = 0; nt < 4; nt++) {
                uint2 t = *(const uint2*)&sB[((warp_n * 4 + nt) * 2 + ks) * 64 + lfrag * 2];
                bf[nt][0] = t.x; bf[nt][1] = t.y;
            }
#pragma unroll
            for (int mt = 0; mt < 4; mt++)
#pragma unroll
                for (int nt = 0; nt < 4; nt++)
                    mma_tf32(acc[mt][nt], af[mt][0], af[mt][1], af[mt][2],
                             af[mt][3], bf[nt][0], bf[nt][1]);
        }
        __syncthreads();
    }

    if (rope) {
        const float lg = logf(10000.0f);
#pragma unroll
        for (int mt = 0; mt < 4; mt++) {
            int r0 = bm + warp_m * 64 + mt * 16 + gid;
            float p0 = (float)pos[r0 & (SEQ - 1)];
            float p1 = (float)pos[(r0 + 8) & (SEQ - 1)];
#pragma unroll
            for (int nt = 0; nt < 4; nt++) {
                int c = bn + warp_n * 32 + nt * 8 + 2 * tig;
                int d = c & (D_K - 1);   // even index within head
                float invf = expf(-lg * ((float)d / (float)D_K));
                float sn0, cs0, sn1, cs1;
                sincosf(p0 * invf, &sn0, &cs0);
                sincosf(p1 * invf, &sn1, &cs1);
                float v0 = acc[mt][nt][0], v1 = acc[mt][nt][1];
                float w0 = acc[mt][nt][2], w1 = acc[mt][nt][3];
                *(float2*)&C[(size_t)r0 * D_MODEL + c] =
                    make_float2(v0 * cs0 - v1 * sn0, v0 * sn0 + v1 * cs0);
                *(float2*)&C[(size_t)(r0 + 8) * D_MODEL + c] =
                    make_float2(w0 * cs1 - w1 * sn1, w0 * sn1 + w1 * cs1);
            }
        }
    } else {
#pragma unroll
        for (int mt = 0; mt < 4; mt++) {
            int r0 = bm + warp_m * 64 + mt * 16 + gid;
#pragma unroll
            for (int nt = 0; nt < 4; nt++) {
                int c = bn + warp_n * 32 + nt * 8 + 2 * tig;
                *(float2*)&C[(size_t)r0 * D_MODEL + c] =
                    make_float2(acc[mt][nt][0], acc[mt][nt][1]);
                *(float2*)&C[(size_t)(r0 + 8) * D_MODEL + c] =
                    make_float2(acc[mt][nt][2], acc[mt][nt][3]);
            }
        }
    }
}

// ---------------------------------------------------------------------------
// Flash attention, FA2-style (unchanged from round 3). Br=128, Bc=32, causal.
// ---------------------------------------------------------------------------
__global__ __launch_bounds__(256, 2)
void attn_tf32(const float* __restrict__ Qg, const float* __restrict__ Kg,
               const float* __restrict__ Vg, float* __restrict__ Og)
{
    __shared__ float Ks[32][68];       // natural [k][d]
    __shared__ float Vs[32][72];       // natural [k][d]
    __shared__ float Ps[8][16][36];    // per-warp P tile [q16][k32]

    const int tid = threadIdx.x;
    const int warp = tid >> 5;
    const int lane = tid & 31;
    const int gid = lane >> 2;   // 0..7
    const int tig = lane & 3;    // 0..3

    const int qt = (int)gridDim.x - 1 - (int)blockIdx.x;  // heavy blocks first
    const int bh = blockIdx.y;
    const int q0 = qt * 128;
    const size_t base = (size_t)(bh >> 4) * SEQ * D_MODEL + (size_t)(bh & 15) * D_K;

    const int qw = q0 + warp * 16;          // warp's first q row
    const int rowmax = qw + 15;

    uint32_t qa[8][4];
    {
        const float* Qr0 = Qg + base + (size_t)(qw + gid) * D_MODEL;
        const float* Qr1 = Qr0 + 8 * D_MODEL;
#pragma unroll
        for (int ks = 0; ks < 8; ks++) {
            qa[ks][0] = f2tf32(Qr0[ks * 8 + tig] * 0.125f);
            qa[ks][1] = f2tf32(Qr1[ks * 8 + tig] * 0.125f);
            qa[ks][2] = f2tf32(Qr0[ks * 8 + tig + 4] * 0.125f);
            qa[ks][3] = f2tf32(Qr1[ks * 8 + tig + 4] * 0.125f);
        }
    }

    float of[8][4];
#pragma unroll
    for (int i = 0; i < 8; i++)
#pragma unroll
        for (int j = 0; j < 4; j++) of[i][j] = 0.0f;
    float m0 = -1e30f, m1 = -1e30f, l0 = 0.0f, l1 = 0.0f;

    const int nkb = (q0 + 128) / 32;   // 4*qt + 4

    for (int kb = 0; kb < nkb; kb++) {
        const int k0 = kb * 32;
#pragma unroll
        for (int i = 0; i < 2; i++) {
            int idx = tid + i * 256;
            int k = idx >> 4;
            int d = (idx & 15) * 4;
            float4 kv = *(const float4*)&Kg[base + (size_t)(k0 + k) * D_MODEL + d];
            float4 vv = *(const float4*)&Vg[base + (size_t)(k0 + k) * D_MODEL + d];
            Ks[k][d + 0] = __uint_as_float(f2tf32(kv.x));
            Ks[k][d + 1] = __uint_as_float(f2tf32(kv.y));
            Ks[k][d + 2] = __uint_as_float(f2tf32(kv.z));
            Ks[k][d + 3] = __uint_as_float(f2tf32(kv.w));
            Vs[k][d + 0] = __uint_as_float(f2tf32(vv.x));
            Vs[k][d + 1] = __uint_as_float(f2tf32(vv.y));
            Vs[k][d + 2] = __uint_as_float(f2tf32(vv.z));
            Vs[k][d + 3] = __uint_as_float(f2tf32(vv.w));
        }
        __syncthreads();

        if (k0 <= rowmax) {
            float sc[4][4];
#pragma unroll
            for (int nt = 0; nt < 4; nt++)
#pragma unroll
                for (int v = 0; v < 4; v++) sc[nt][v] = 0.0f;
#pragma unroll
            for (int ks = 0; ks < 8; ks++) {
#pragma unroll
                for (int nt = 0; nt < 4; nt++) {
                    int kc = nt * 8 + gid;
                    uint32_t b0 = __float_as_uint(Ks[kc][ks * 8 + tig]);
                    uint32_t b1 = __float_as_uint(Ks[kc][ks * 8 + tig + 4]);
                    mma_tf32(sc[nt], qa[ks][0], qa[ks][1], qa[ks][2], qa[ks][3],
                             b0, b1);
                }
            }

            if (k0 + 31 > qw) {
                int r0g = qw + gid;
                int r1g = r0g + 8;
#pragma unroll
                for (int nt = 0; nt < 4; nt++) {
                    int c = k0 + nt * 8 + 2 * tig;
                    if (c > r0g)     sc[nt][0] = -1e30f;
                    if (c + 1 > r0g) sc[nt][1] = -1e30f;
                    if (c > r1g)     sc[nt][2] = -1e30f;
                    if (c + 1 > r1g) sc[nt][3] = -1e30f;
                }
            }

            float mx0 = sc[0][0], mx1 = sc[0][2];
#pragma unroll
            for (int nt = 0; nt < 4; nt++) {
                mx0 = fmaxf(mx0, fmaxf(sc[nt][0], sc[nt][1]));
                mx1 = fmaxf(mx1, fmaxf(sc[nt][2], sc[nt][3]));
            }
            mx0 = fmaxf(mx0, __shfl_xor_sync(0xffffffffu, mx0, 1));
            mx0 = fmaxf(mx0, __shfl_xor_sync(0xffffffffu, mx0, 2));
            mx1 = fmaxf(mx1, __shfl_xor_sync(0xffffffffu, mx1, 1));
            mx1 = fmaxf(mx1, __shfl_xor_sync(0xffffffffu, mx1, 2));

            float mn0 = fmaxf(m0, mx0);
            float mn1 = fmaxf(m1, mx1);
            float al0 = __expf(m0 - mn0);
            float al1 = __expf(m1 - mn1);
            m0 = mn0; m1 = mn1;

            float sum0 = 0.0f, sum1 = 0.0f;
#pragma unroll
            for (int nt = 0; nt < 4; nt++) {
                float p0 = __expf(sc[nt][0] - mn0);
                float p1 = __expf(sc[nt][1] - mn0);
                float p2 = __expf(sc[nt][2] - mn1);
                float p3 = __expf(sc[nt][3] - mn1);
                sum0 += p0 + p1;
                sum1 += p2 + p3;
                sc[nt][0] = __uint_as_float(f2tf32(p0));
                sc[nt][1] = __uint_as_float(f2tf32(p1));
                sc[nt][2] = __uint_as_float(f2tf32(p2));
                sc[nt][3] = __uint_as_float(f2tf32(p3));
            }
            sum0 += __shfl_xor_sync(0xffffffffu, sum0, 1);
            sum0 += __shfl_xor_sync(0xffffffffu, sum0, 2);
            sum1 += __shfl_xor_sync(0xffffffffu, sum1, 1);
            sum1 += __shfl_xor_sync(0xffffffffu, sum1, 2);
            l0 = l0 * al0 + sum0;
            l1 = l1 * al1 + sum1;

#pragma unroll
            for (int nt = 0; nt < 8; nt++) {
                of[nt][0] *= al0; of[nt][1] *= al0;
                of[nt][2] *= al1; of[nt][3] *= al1;
            }

#pragma unroll
            for (int nt = 0; nt < 4; nt++) {
                *(float2*)&Ps[warp][gid][nt * 8 + 2 * tig] =
                    make_float2(sc[nt][0], sc[nt][1]);
                *(float2*)&Ps[warp][gid + 8][nt * 8 + 2 * tig] =
                    make_float2(sc[nt][2], sc[nt][3]);
            }
            __syncwarp();

#pragma unroll
            for (int ks = 0; ks < 4; ks++) {
                uint32_t a0 = __float_as_uint(Ps[warp][gid][ks * 8 + tig]);
                uint32_t a1 = __float_as_uint(Ps[warp][gid + 8][ks * 8 + tig]);
                uint32_t a2 = __float_as_uint(Ps[warp][gid][ks * 8 + tig + 4]);
                uint32_t a3 = __float_as_uint(Ps[warp][gid + 8][ks * 8 + tig + 4]);
#pragma unroll
                for (int nt = 0; nt < 8; nt++) {
                    int dc = nt * 8 + gid;
                    uint32_t b0 = __float_as_uint(Vs[ks * 8 + tig][dc]);
                    uint32_t b1 = __float_as_uint(Vs[ks * 8 + tig + 4][dc]);
                    mma_tf32(of[nt], a0, a1, a2, a3, b0, b1);
                }
            }
            __syncwarp();
        }
        __syncthreads();
    }

    {
        float inv0 = 1.0f / l0;
        float inv1 = 1.0f / l1;
        float* O0 = Og + base + (size_t)(qw + gid) * D_MODEL;
        float* O1 = O0 + 8 * D_MODEL;
#pragma unroll
        for (int nt = 0; nt < 8; nt++) {
            int c = nt * 8 + 2 * tig;
            *(float2*)&O0[c] = make_float2(of[nt][0] * inv0, of[nt][1] * inv0);
            *(float2*)&O1[c] = make_float2(of[nt][2] * inv1, of[nt][3] * inv1);
        }
    }
}

// ---------------------------------------------------------------------------
extern "C" void kernel_launch(void* const* d_in, const int* in_sizes, int n_in,
                              void* d_out, int out_size)
{
    const float* x  = (const float*)d_in[0];
    const float* wq = (const float*)d_in[1];
    const float* wk = (const float*)d_in[2];
    const float* wv = (const float*)d_in[3];
    const float* wo = (const float*)d_in[4];
    const int* tok  = (const int*)d_in[5];
    float* out = (float*)d_out;

    float *qp, *kp, *vp, *op;
    cudaGetSymbolAddress((void**)&qp, g_q);
    cudaGetSymbolAddress((void**)&kp, g_k);
    cudaGetSymbolAddress((void**)&vp, g_v);
    cudaGetSymbolAddress((void**)&op, g_o);

    dim3 gg(D_MODEL / 128, MTOT / 128);   // (8, 64)
    gemm_tf32<<<gg, 256>>>(x, wq, qp, 1, tok);
    gemm_tf32<<<gg, 256>>>(x, wk, kp, 1, tok);
    gemm_tf32<<<gg, 256>>>(x, wv, vp, 0, nullptr);

    dim3 ga(SEQ / 128, BATCH * NUM_HEADS); // (16, 64)
    attn_tf32<<<ga, 256>>>(qp, kp, vp, op);

    gemm_tf32<<<gg, 256>>>(op, wo, out, 0, nullptr);
}

// round 6
// speedup vs baseline: 1.8072x; 1.8072x over previous
#include <cuda_runtime.h>
#include <cuda_fp16.h>
#include <math.h>
#include <stdint.h>

#define D_MODEL 1024
#define NUM_HEADS 16
#define SEQ 2048
#define BATCH 4
#define D_K 64
#define MTOT (BATCH * SEQ)   // 8192

// Scratch (static device globals; no runtime allocation allowed)
__device__ float g_q[MTOT * D_MODEL];
__device__ float g_k[MTOT * D_MODEL];
__device__ float g_v[MTOT * D_MODEL];
__device__ float g_o[MTOT * D_MODEL];

// ---------------------------------------------------------------------------
// helpers
// ---------------------------------------------------------------------------
__device__ __forceinline__ uint32_t pack2(float lo, float hi) {
    // d = {hi:16, lo:16}; PTX cvt.f16x2 puts first source in high half
    uint32_t r;
    asm("cvt.rn.f16x2.f32 %0, %1, %2;" : "=r"(r) : "f"(hi), "f"(lo));
    return r;
}

__device__ __forceinline__ void mma_f16(float c[4], uint32_t a0, uint32_t a1,
                                        uint32_t a2, uint32_t a3,
                                        uint32_t b0, uint32_t b1) {
    asm volatile(
        "mma.sync.aligned.m16n8k16.row.col.f32.f16.f16.f32 "
        "{%0,%1,%2,%3},{%4,%5,%6,%7},{%8,%9},{%0,%1,%2,%3};"
        : "+f"(c[0]), "+f"(c[1]), "+f"(c[2]), "+f"(c[3])
        : "r"(a0), "r"(a1), "r"(a2), "r"(a3), "r"(b0), "r"(b1));
}

__device__ __forceinline__ void ldm4(uint32_t (&r)[4], uint32_t addr) {
    asm volatile("ldmatrix.sync.aligned.m8n8.x4.shared.b16 {%0,%1,%2,%3}, [%4];"
                 : "=r"(r[0]), "=r"(r[1]), "=r"(r[2]), "=r"(r[3]) : "r"(addr));
}
__device__ __forceinline__ void ldm4t(uint32_t (&r)[4], uint32_t addr) {
    asm volatile("ldmatrix.sync.aligned.m8n8.x4.trans.shared.b16 {%0,%1,%2,%3}, [%4];"
                 : "=r"(r[0]), "=r"(r[1]), "=r"(r[2]), "=r"(r[3]) : "r"(addr));
}

__device__ __forceinline__ uint32_t smem_u32(const void* p) {
    return (uint32_t)__cvta_generic_to_shared(p);
}

// ---------------------------------------------------------------------------
// fp16 tensor-core GEMM (f32 accum), NT form: C[m,n] = sum_k A[m,k]*B[n,k]
// Block tile 128x128, BK=16 (one k16 mma step), double-buffered smem.
// smem rows: 16 fp16 = 8 words + 4 pad = 12 words (48B; odd*16B mod 128 ->
// conflict-free ldmatrix). 256 threads = 8 warps (2x4), warp tile 64x32.
// rope != 0: RoPE on (even,odd) pairs per 64-wide head slice.
// ---------------------------------------------------------------------------
__global__ __launch_bounds__(256, 2)
void gemm_f16(const float* __restrict__ A, const float* __restrict__ B,
              float* __restrict__ C, int rope, const int* __restrict__ pos)
{
    __shared__ __align__(16) uint32_t As[2][1536];   // 128 rows x 12 words
    __shared__ __align__(16) uint32_t Bs[2][1536];

    const int tid = threadIdx.x;
    const int warp = tid >> 5;
    const int lane = tid & 31;
    const int gid = lane >> 2;       // 0..7
    const int tig = lane & 3;        // 0..3
    const int warp_m = warp >> 2;    // 0..1
    const int warp_n = warp & 3;     // 0..3

    const int bm = blockIdx.y * 128;
    const int bn = blockIdx.x * 128;

    // loader: thread owns row r, k-half h (8 consecutive k)
    const int r = tid >> 1;
    const int h = tid & 1;
    const int sts_off = r * 12 + h * 4;   // word offset

    // ldmatrix lane address bases (word offsets within a stage)
    const int l = lane;
    const uint32_t a_base =
        (uint32_t)((warp_m * 64 + (l & 7) + 8 * ((l >> 3) & 1)) * 12 +
                   4 * ((l >> 4) & 1)) * 4;
    const uint32_t b_base =
        (uint32_t)((warp_n * 32 + (l & 7) + 8 * ((l >> 4) & 1)) * 12 +
                   4 * ((l >> 3) & 1)) * 4;
    const uint32_t sA = smem_u32(&As[0][0]);
    const uint32_t sB = smem_u32(&Bs[0][0]);

    float acc[4][4][4];
#pragma unroll
    for (int i = 0; i < 4; i++)
#pragma unroll
        for (int j = 0; j < 4; j++)
#pragma unroll
            for (int v = 0; v < 4; v++) acc[i][j][v] = 0.0f;

    const float* Arow = A + (size_t)(bm + r) * D_MODEL + h * 8;
    const float* Brow = B + (size_t)(bn + r) * D_MODEL + h * 8;

    float4 ra0, ra1, rb0, rb1;
    ra0 = *(const float4*)&Arow[0];
    ra1 = *(const float4*)&Arow[4];
    rb0 = *(const float4*)&Brow[0];
    rb1 = *(const float4*)&Brow[4];
    // store stage 0
    {
        uint4 wa = make_uint4(pack2(ra0.x, ra0.y), pack2(ra0.z, ra0.w),
                              pack2(ra1.x, ra1.y), pack2(ra1.z, ra1.w));
        uint4 wb = make_uint4(pack2(rb0.x, rb0.y), pack2(rb0.z, rb0.w),
                              pack2(rb1.x, rb1.y), pack2(rb1.z, rb1.w));
        *(uint4*)&As[0][sts_off] = wa;
        *(uint4*)&Bs[0][sts_off] = wb;
    }

    const int NKT = D_MODEL / 16;   // 64
    for (int kt = 0; kt < NKT; kt++) {
        __syncthreads();
        const int cur = kt & 1;
        const uint32_t stg = (uint32_t)cur * 6144u;

        if (kt + 1 < NKT) {
            const float* An = Arow + (kt + 1) * 16;
            const float* Bn = Brow + (kt + 1) * 16;
            ra0 = *(const float4*)&An[0];
            ra1 = *(const float4*)&An[4];
            rb0 = *(const float4*)&Bn[0];
            rb1 = *(const float4*)&Bn[4];
        }

        uint32_t af[4][4], bf[2][4];
#pragma unroll
        for (int mt = 0; mt < 4; mt++)
            ldm4(af[mt], sA + stg + a_base + (uint32_t)mt * 768u);
#pragma unroll
        for (int p = 0; p < 2; p++)
            ldm4(bf[p], sB + stg + b_base + (uint32_t)p * 768u);

#pragma unroll
        for (int mt = 0; mt < 4; mt++)
#pragma unroll
            for (int nt = 0; nt < 4; nt++)
                mma_f16(acc[mt][nt], af[mt][0], af[mt][1], af[mt][2], af[mt][3],
                        bf[nt >> 1][(nt & 1) * 2], bf[nt >> 1][(nt & 1) * 2 + 1]);

        if (kt + 1 < NKT) {
            uint4 wa = make_uint4(pack2(ra0.x, ra0.y), pack2(ra0.z, ra0.w),
                                  pack2(ra1.x, ra1.y), pack2(ra1.z, ra1.w));
            uint4 wb = make_uint4(pack2(rb0.x, rb0.y), pack2(rb0.z, rb0.w),
                                  pack2(rb1.x, rb1.y), pack2(rb1.z, rb1.w));
            const int nxt = cur ^ 1;
            *(uint4*)&As[nxt][sts_off] = wa;
            *(uint4*)&Bs[nxt][sts_off] = wb;
        }
    }

    if (rope) {
        const float lg = logf(10000.0f);
#pragma unroll
        for (int mt = 0; mt < 4; mt++) {
            int r0 = bm + warp_m * 64 + mt * 16 + gid;
            float p0 = (float)pos[r0 & (SEQ - 1)];
            float p1 = (float)pos[(r0 + 8) & (SEQ - 1)];
#pragma unroll
            for (int nt = 0; nt < 4; nt++) {
                int c = bn + warp_n * 32 + nt * 8 + 2 * tig;
                int d = c & (D_K - 1);   // even index within head
                float invf = expf(-lg * ((float)d / (float)D_K));
                float sn0, cs0, sn1, cs1;
                sincosf(p0 * invf, &sn0, &cs0);
                sincosf(p1 * invf, &sn1, &cs1);
                float v0 = acc[mt][nt][0], v1 = acc[mt][nt][1];
                float w0 = acc[mt][nt][2], w1 = acc[mt][nt][3];
                *(float2*)&C[(size_t)r0 * D_MODEL + c] =
                    make_float2(v0 * cs0 - v1 * sn0, v0 * sn0 + v1 * cs0);
                *(float2*)&C[(size_t)(r0 + 8) * D_MODEL + c] =
                    make_float2(w0 * cs1 - w1 * sn1, w0 * sn1 + w1 * cs1);
            }
        }
    } else {
#pragma unroll
        for (int mt = 0; mt < 4; mt++) {
            int r0 = bm + warp_m * 64 + mt * 16 + gid;
#pragma unroll
            for (int nt = 0; nt < 4; nt++) {
                int c = bn + warp_n * 32 + nt * 8 + 2 * tig;
                *(float2*)&C[(size_t)r0 * D_MODEL + c] =
                    make_float2(acc[mt][nt][0], acc[mt][nt][1]);
                *(float2*)&C[(size_t)(r0 + 8) * D_MODEL + c] =
                    make_float2(acc[mt][nt][2], acc[mt][nt][3]);
            }
        }
    }
}

// ---------------------------------------------------------------------------
// Flash attention, fp16 mma (f32 accum/softmax). Br=128, Bc=32, dk=64, causal.
// 8 warps x 16 q rows; Q frags in registers; K via ldmatrix.x4;
// V via ldmatrix.x4.trans; P stays in registers (S C-frag == PV A-frag).
// smem rows padded to 36 words (144B) -> conflict-free ldmatrix.
// ---------------------------------------------------------------------------
__global__ __launch_bounds__(256, 2)
void attn_f16(const float* __restrict__ Qg, const float* __restrict__ Kg,
              const float* __restrict__ Vg, float* __restrict__ Og)
{
    __shared__ __align__(16) uint32_t Ks[32 * 36];   // [k][d] fp16, 36 words/row
    __shared__ __align__(16) uint32_t Vs[32 * 36];

    const int tid = threadIdx.x;
    const int warp = tid >> 5;
    const int lane = tid & 31;
    const int gid = lane >> 2;   // 0..7
    const int tig = lane & 3;    // 0..3

    const int qt = (int)gridDim.x - 1 - (int)blockIdx.x;  // heavy blocks first
    const int bh = blockIdx.y;
    const int q0 = qt * 128;
    const size_t base = (size_t)(bh >> 4) * SEQ * D_MODEL + (size_t)(bh & 15) * D_K;

    const int qw = q0 + warp * 16;          // warp's first q row
    const int rowmax = qw + 15;

    // ldmatrix lane bases
    const int l = lane;
    const uint32_t k_base = smem_u32(Ks) +
        (uint32_t)(((l & 7) + 8 * ((l >> 4) & 1)) * 36 + 4 * ((l >> 3) & 1)) * 4;
    const uint32_t v_base = smem_u32(Vs) +
        (uint32_t)(((l & 7) + 8 * ((l >> 3) & 1)) * 36 + 4 * ((l >> 4) & 1)) * 4;

    // Q fragments (scaled by 1/sqrt(dk)), fp16x2 packed, loaded once
    uint32_t qa[4][4];
    {
        const float* Qr0 = Qg + base + (size_t)(qw + gid) * D_MODEL;
        const float* Qr1 = Qr0 + 8 * D_MODEL;
#pragma unroll
        for (int ks = 0; ks < 4; ks++) {
            float2 x0 = *(const float2*)&Qr0[ks * 16 + 2 * tig];
            float2 x1 = *(const float2*)&Qr1[ks * 16 + 2 * tig];
            float2 x2 = *(const float2*)&Qr0[ks * 16 + 2 * tig + 8];
            float2 x3 = *(const float2*)&Qr1[ks * 16 + 2 * tig + 8];
            qa[ks][0] = pack2(x0.x * 0.125f, x0.y * 0.125f);
            qa[ks][1] = pack2(x1.x * 0.125f, x1.y * 0.125f);
            qa[ks][2] = pack2(x2.x * 0.125f, x2.y * 0.125f);
            qa[ks][3] = pack2(x3.x * 0.125f, x3.y * 0.125f);
        }
    }

    float of[8][4];
#pragma unroll
    for (int i = 0; i < 8; i++)
#pragma unroll
        for (int j = 0; j < 4; j++) of[i][j] = 0.0f;
    float m0 = -1e30f, m1 = -1e30f, l0 = 0.0f, l1 = 0.0f;

    // K/V loader geometry
    const int kr = tid >> 3;          // 0..31
    const int d8 = tid & 7;           // 0..7 -> d = d8*8
    const int kv_sts = kr * 36 + d8 * 4;

    const int nkb = (q0 + 128) / 32;   // 4*qt + 4

    for (int kb = 0; kb < nkb; kb++) {
        const int k0 = kb * 32;
        {
            const float* Kr = Kg + base + (size_t)(k0 + kr) * D_MODEL + d8 * 8;
            const float* Vr = Vg + base + (size_t)(k0 + kr) * D_MODEL + d8 * 8;
            float4 ka = *(const float4*)&Kr[0];
            float4 kc = *(const float4*)&Kr[4];
            float4 va = *(const float4*)&Vr[0];
            float4 vc = *(const float4*)&Vr[4];
            *(uint4*)&Ks[kv_sts] = make_uint4(pack2(ka.x, ka.y), pack2(ka.z, ka.w),
                                              pack2(kc.x, kc.y), pack2(kc.z, kc.w));
            *(uint4*)&Vs[kv_sts] = make_uint4(pack2(va.x, va.y), pack2(va.z, va.w),
                                              pack2(vc.x, vc.y), pack2(vc.z, vc.w));
        }
        __syncthreads();

        if (k0 <= rowmax) {
            // S = Q K^T : 4 k16-steps x 4 n-atoms
            float sc[4][4];
#pragma unroll
            for (int nt = 0; nt < 4; nt++)
#pragma unroll
                for (int v = 0; v < 4; v++) sc[nt][v] = 0.0f;
#pragma unroll
            for (int ks = 0; ks < 4; ks++) {
                uint32_t kb0[4], kb1[4];
                ldm4(kb0, k_base + (uint32_t)ks * 32u);            // kc 0-15
                ldm4(kb1, k_base + 2304u + (uint32_t)ks * 32u);    // kc 16-31
                mma_f16(sc[0], qa[ks][0], qa[ks][1], qa[ks][2], qa[ks][3],
                        kb0[0], kb0[1]);
                mma_f16(sc[1], qa[ks][0], qa[ks][1], qa[ks][2], qa[ks][3],
                        kb0[2], kb0[3]);
                mma_f16(sc[2], qa[ks][0], qa[ks][1], qa[ks][2], qa[ks][3],
                        kb1[0], kb1[1]);
                mma_f16(sc[3], qa[ks][0], qa[ks][1], qa[ks][2], qa[ks][3],
                        kb1[2], kb1[3]);
            }

            // causal mask (only diagonal-overlapping blocks)
            if (k0 + 31 > qw) {
                int r0g = qw + gid;
                int r1g = r0g + 8;
#pragma unroll
                for (int nt = 0; nt < 4; nt++) {
                    int c = k0 + nt * 8 + 2 * tig;
                    if (c > r0g)     sc[nt][0] = -1e30f;
                    if (c + 1 > r0g) sc[nt][1] = -1e30f;
                    if (c > r1g)     sc[nt][2] = -1e30f;
                    if (c + 1 > r1g) sc[nt][3] = -1e30f;
                }
            }

            // online softmax (registers + quad shfl)
            float mx0 = sc[0][0], mx1 = sc[0][2];
#pragma unroll
            for (int nt = 0; nt < 4; nt++) {
                mx0 = fmaxf(mx0, fmaxf(sc[nt][0], sc[nt][1]));
                mx1 = fmaxf(mx1, fmaxf(sc[nt][2], sc[nt][3]));
            }
            mx0 = fmaxf(mx0, __shfl_xor_sync(0xffffffffu, mx0, 1));
            mx0 = fmaxf(mx0, __shfl_xor_sync(0xffffffffu, mx0, 2));
            mx1 = fmaxf(mx1, __shfl_xor_sync(0xffffffffu, mx1, 1));
            mx1 = fmaxf(mx1, __shfl_xor_sync(0xffffffffu, mx1, 2));

            float mn0 = fmaxf(m0, mx0);
            float mn1 = fmaxf(m1, mx1);
            float al0 = __expf(m0 - mn0);
            float al1 = __expf(m1 - mn1);
            m0 = mn0; m1 = mn1;

            float sum0 = 0.0f, sum1 = 0.0f;
#pragma unroll
            for (int nt = 0; nt < 4; nt++) {
                sc[nt][0] = __expf(sc[nt][0] - mn0);
                sc[nt][1] = __expf(sc[nt][1] - mn0);
                sc[nt][2] = __expf(sc[nt][2] - mn1);
                sc[nt][3] = __expf(sc[nt][3] - mn1);
                sum0 += sc[nt][0] + sc[nt][1];
                sum1 += sc[nt][2] + sc[nt][3];
            }
            sum0 += __shfl_xor_sync(0xffffffffu, sum0, 1);
            sum0 += __shfl_xor_sync(0xffffffffu, sum0, 2);
            sum1 += __shfl_xor_sync(0xffffffffu, sum1, 1);
            sum1 += __shfl_xor_sync(0xffffffffu, sum1, 2);
            l0 = l0 * al0 + sum0;
            l1 = l1 * al1 + sum1;

            // rescale O
#pragma unroll
            for (int nt = 0; nt < 8; nt++) {
                of[nt][0] *= al0; of[nt][1] *= al0;
                of[nt][2] *= al1; of[nt][3] *= al1;
            }

            // pack P to fp16 A-fragments (S C-frag == PV A-frag layout)
            uint32_t pa[2][4];
#pragma unroll
            for (int s = 0; s < 2; s++) {
                pa[s][0] = pack2(sc[2 * s][0], sc[2 * s][1]);
                pa[s][1] = pack2(sc[2 * s][2], sc[2 * s][3]);
                pa[s][2] = pack2(sc[2 * s + 1][0], sc[2 * s + 1][1]);
                pa[s][3] = pack2(sc[2 * s + 1][2], sc[2 * s + 1][3]);
            }

            // O += P @ V : 2 k16-steps x 8 d-atoms, V via ldmatrix.trans
#pragma unroll
            for (int s = 0; s < 2; s++) {
#pragma unroll
                for (int dp = 0; dp < 4; dp++) {
                    uint32_t vb[4];
                    ldm4t(vb, v_base + (uint32_t)s * 2304u + (uint32_t)dp * 32u);
                    mma_f16(of[dp * 2], pa[s][0], pa[s][1], pa[s][2], pa[s][3],
                            vb[0], vb[1]);
                    mma_f16(of[dp * 2 + 1], pa[s][0], pa[s][1], pa[s][2], pa[s][3],
                            vb[2], vb[3]);
                }
            }
        }
        __syncthreads();
    }

    // normalize + write
    {
        float inv0 = 1.0f / l0;
        float inv1 = 1.0f / l1;
        float* O0 = Og + base + (size_t)(qw + gid) * D_MODEL;
        float* O1 = O0 + 8 * D_MODEL;
#pragma unroll
        for (int nt = 0; nt < 8; nt++) {
            int c = nt * 8 + 2 * tig;
            *(float2*)&O0[c] = make_float2(of[nt][0] * inv0, of[nt][1] * inv0);
            *(float2*)&O1[c] = make_float2(of[nt][2] * inv1, of[nt][3] * inv1);
        }
    }
}

// ---------------------------------------------------------------------------
extern "C" void kernel_launch(void* const* d_in, const int* in_sizes, int n_in,
                              void* d_out, int out_size)
{
    const float* x  = (const float*)d_in[0];
    const float* wq = (const float*)d_in[1];
    const float* wk = (const float*)d_in[2];
    const float* wv = (const float*)d_in[3];
    const float* wo = (const float*)d_in[4];
    const int* tok  = (const int*)d_in[5];
    float* out = (float*)d_out;

    float *qp, *kp, *vp, *op;
    cudaGetSymbolAddress((void**)&qp, g_q);
    cudaGetSymbolAddress((void**)&kp, g_k);
    cudaGetSymbolAddress((void**)&vp, g_v);
    cudaGetSymbolAddress((void**)&op, g_o);

    dim3 gg(D_MODEL / 128, MTOT / 128);   // (8, 64)
    gemm_f16<<<gg, 256>>>(x, wq, qp, 1, tok);
    gemm_f16<<<gg, 256>>>(x, wk, kp, 1, tok);
    gemm_f16<<<gg, 256>>>(x, wv, vp, 0, nullptr);

    dim3 ga(SEQ / 128, BATCH * NUM_HEADS); // (16, 64)
    attn_f16<<<ga, 256>>>(qp, kp, vp, op);

    gemm_f16<<<gg, 256>>>(op, wo, out, 0, nullptr);
}

// round 7
// speedup vs baseline: 2.3061x; 1.2761x over previous
#include <cuda_runtime.h>
#include <cuda_fp16.h>
#include <math.h>
#include <stdint.h>

#define D_MODEL 1024
#define NUM_HEADS 16
#define SEQ 2048
#define BATCH 4
#define D_K 64
#define MTOT (BATCH * SEQ)   // 8192

// fp16 scratch (static device globals; no runtime allocation allowed)
__device__ __align__(16) __half g_xh[MTOT * D_MODEL];
__device__ __align__(16) __half g_qh[MTOT * D_MODEL];
__device__ __align__(16) __half g_kh[MTOT * D_MODEL];
__device__ __align__(16) __half g_vh[MTOT * D_MODEL];
__device__ __align__(16) __half g_oh[MTOT * D_MODEL];
__device__ __align__(16) __half g_wqh[D_MODEL * D_MODEL];
__device__ __align__(16) __half g_wkh[D_MODEL * D_MODEL];
__device__ __align__(16) __half g_wvh[D_MODEL * D_MODEL];
__device__ __align__(16) __half g_woh[D_MODEL * D_MODEL];

// ---------------------------------------------------------------------------
// helpers
// ---------------------------------------------------------------------------
__device__ __forceinline__ uint32_t pack2(float lo, float hi) {
    uint32_t r;
    asm("cvt.rn.f16x2.f32 %0, %1, %2;" : "=r"(r) : "f"(hi), "f"(lo));
    return r;
}

__device__ __forceinline__ void mma_f16(float c[4], uint32_t a0, uint32_t a1,
                                        uint32_t a2, uint32_t a3,
                                        uint32_t b0, uint32_t b1) {
    asm volatile(
        "mma.sync.aligned.m16n8k16.row.col.f32.f16.f16.f32 "
        "{%0,%1,%2,%3},{%4,%5,%6,%7},{%8,%9},{%0,%1,%2,%3};"
        : "+f"(c[0]), "+f"(c[1]), "+f"(c[2]), "+f"(c[3])
        : "r"(a0), "r"(a1), "r"(a2), "r"(a3), "r"(b0), "r"(b1));
}

__device__ __forceinline__ void ldm4(uint32_t (&r)[4], uint32_t addr) {
    asm volatile("ldmatrix.sync.aligned.m8n8.x4.shared.b16 {%0,%1,%2,%3}, [%4];"
                 : "=r"(r[0]), "=r"(r[1]), "=r"(r[2]), "=r"(r[3]) : "r"(addr));
}
__device__ __forceinline__ void ldm4t(uint32_t (&r)[4], uint32_t addr) {
    asm volatile("ldmatrix.sync.aligned.m8n8.x4.trans.shared.b16 {%0,%1,%2,%3}, [%4];"
                 : "=r"(r[0]), "=r"(r[1]), "=r"(r[2]), "=r"(r[3]) : "r"(addr));
}

__device__ __forceinline__ uint32_t smem_u32(const void* p) {
    return (uint32_t)__cvta_generic_to_shared(p);
}

// ---------------------------------------------------------------------------
// fp32 -> fp16 pre-pass: x, and the 4 weights (wq scaled by 1/sqrt(dk)=0.125)
// ---------------------------------------------------------------------------
__global__ void to_half(const float4* __restrict__ x, const float4* __restrict__ wq,
                        const float4* __restrict__ wk, const float4* __restrict__ wv,
                        const float4* __restrict__ wo)
{
    const int NX = MTOT * D_MODEL / 4;
    const int NW = D_MODEL * D_MODEL / 4;
    const int stride = gridDim.x * blockDim.x;
    uint2* xh = (uint2*)g_xh;
    uint2* wqh = (uint2*)g_wqh;
    uint2* wkh = (uint2*)g_wkh;
    uint2* wvh = (uint2*)g_wvh;
    uint2* woh = (uint2*)g_woh;

    for (int i = blockIdx.x * blockDim.x + threadIdx.x; i < NX; i += stride) {
        float4 v = x[i];
        xh[i] = make_uint2(pack2(v.x, v.y), pack2(v.z, v.w));
    }
    for (int i = blockIdx.x * blockDim.x + threadIdx.x; i < NW; i += stride) {
        float4 a = wq[i];
        wqh[i] = make_uint2(pack2(a.x * 0.125f, a.y * 0.125f),
                            pack2(a.z * 0.125f, a.w * 0.125f));
        float4 b = wk[i];
        wkh[i] = make_uint2(pack2(b.x, b.y), pack2(b.z, b.w));
        float4 c = wv[i];
        wvh[i] = make_uint2(pack2(c.x, c.y), pack2(c.z, c.w));
        float4 d = wo[i];
        woh[i] = make_uint2(pack2(d.x, d.y), pack2(d.z, d.w));
    }
}

// ---------------------------------------------------------------------------
// fp16-in GEMM mainloop shared by QKV (fp16 out + optional RoPE) and WO
// (fp32 out). Block tile 128x128, BK=16, double-buffered smem (rows of
// 16 fp16 = 8 words + 4 pad). 256 threads = 8 warps (2x4), warp tile 64x32.
// ---------------------------------------------------------------------------
struct GemmFrag { float acc[4][4][4]; };

__device__ __forceinline__ void gemm_mainloop(
    const __half* __restrict__ A, const __half* __restrict__ B,
    int bm, int bn, uint32_t* As, uint32_t* Bs, float (&acc)[4][4][4])
{
    const int tid = threadIdx.x;
    const int lane = tid & 31;
    const int warp = tid >> 5;
    const int warp_m = warp >> 2;
    const int warp_n = warp & 3;

    const int r = tid >> 1;
    const int h = tid & 1;
    const int sts_off = r * 12 + h * 4;

    const int l = lane;
    const uint32_t a_base =
        (uint32_t)((warp_m * 64 + (l & 7) + 8 * ((l >> 3) & 1)) * 12 +
                   4 * ((l >> 4) & 1)) * 4;
    const uint32_t b_base =
        (uint32_t)((warp_n * 32 + (l & 7) + 8 * ((l >> 4) & 1)) * 12 +
                   4 * ((l >> 3) & 1)) * 4;
    const uint32_t sA = smem_u32(As);
    const uint32_t sB = smem_u32(Bs);

    const uint4* Arow = (const uint4*)(A + (size_t)(bm + r) * D_MODEL);
    const uint4* Brow = (const uint4*)(B + (size_t)(bn + r) * D_MODEL);

    uint4 ra = Arow[h];
    uint4 rb = Brow[h];
    *(uint4*)&As[sts_off] = ra;
    *(uint4*)&Bs[sts_off] = rb;

    const int NKT = D_MODEL / 16;   // 64
    for (int kt = 0; kt < NKT; kt++) {
        __syncthreads();
        const int cur = kt & 1;
        const uint32_t stg = (uint32_t)cur * 6144u;

        if (kt + 1 < NKT) {
            ra = Arow[(kt + 1) * 2 + h];
            rb = Brow[(kt + 1) * 2 + h];
        }

        uint32_t af[4][4], bf[2][4];
#pragma unroll
        for (int mt = 0; mt < 4; mt++)
            ldm4(af[mt], sA + stg + a_base + (uint32_t)mt * 768u);
#pragma unroll
        for (int p = 0; p < 2; p++)
            ldm4(bf[p], sB + stg + b_base + (uint32_t)p * 768u);

#pragma unroll
        for (int mt = 0; mt < 4; mt++)
#pragma unroll
            for (int nt = 0; nt < 4; nt++)
                mma_f16(acc[mt][nt], af[mt][0], af[mt][1], af[mt][2], af[mt][3],
                        bf[nt >> 1][(nt & 1) * 2], bf[nt >> 1][(nt & 1) * 2 + 1]);

        if (kt + 1 < NKT) {
            const int nxt = (cur ^ 1) * 1536;
            *(uint4*)&As[nxt + sts_off] = ra;
            *(uint4*)&Bs[nxt + sts_off] = rb;
        }
    }
}

// Fused QKV projection: grid (24, 64). blockIdx.x>>3 selects matrix (q/k/v),
// fp16 output, RoPE applied for q and k.
__global__ __launch_bounds__(256, 2)
void gemm_qkv(const int* __restrict__ pos)
{
    __shared__ __align__(16) uint32_t As[2 * 1536];
    __shared__ __align__(16) uint32_t Bs[2 * 1536];

    const int mat = blockIdx.x >> 3;
    const int bn = (blockIdx.x & 7) * 128;
    const int bm = blockIdx.y * 128;

    const __half* B = (mat == 0) ? g_wqh : (mat == 1) ? g_wkh : g_wvh;
    __half* C = (mat == 0) ? g_qh : (mat == 1) ? g_kh : g_vh;
    const int rope = (mat < 2);

    float acc[4][4][4];
#pragma unroll
    for (int i = 0; i < 4; i++)
#pragma unroll
        for (int j = 0; j < 4; j++)
#pragma unroll
            for (int v = 0; v < 4; v++) acc[i][j][v] = 0.0f;

    gemm_mainloop(g_xh, B, bm, bn, As, Bs, acc);

    const int lane = threadIdx.x & 31;
    const int warp = threadIdx.x >> 5;
    const int gid = lane >> 2;
    const int tig = lane & 3;
    const int warp_m = warp >> 2;
    const int warp_n = warp & 3;

    if (rope) {
        const float lg = logf(10000.0f);
#pragma unroll
        for (int mt = 0; mt < 4; mt++) {
            int r0 = bm + warp_m * 64 + mt * 16 + gid;
            float p0 = (float)pos[r0 & (SEQ - 1)];
            float p1 = (float)pos[(r0 + 8) & (SEQ - 1)];
#pragma unroll
            for (int nt = 0; nt < 4; nt++) {
                int c = bn + warp_n * 32 + nt * 8 + 2 * tig;
                int d = c & (D_K - 1);
                float invf = expf(-lg * ((float)d / (float)D_K));
                float sn0, cs0, sn1, cs1;
                sincosf(p0 * invf, &sn0, &cs0);
                sincosf(p1 * invf, &sn1, &cs1);
                float v0 = acc[mt][nt][0], v1 = acc[mt][nt][1];
                float w0 = acc[mt][nt][2], w1 = acc[mt][nt][3];
                *(uint32_t*)&C[(size_t)r0 * D_MODEL + c] =
                    pack2(v0 * cs0 - v1 * sn0, v0 * sn0 + v1 * cs0);
                *(uint32_t*)&C[(size_t)(r0 + 8) * D_MODEL + c] =
                    pack2(w0 * cs1 - w1 * sn1, w0 * sn1 + w1 * cs1);
            }
        }
    } else {
#pragma unroll
        for (int mt = 0; mt < 4; mt++) {
            int r0 = bm + warp_m * 64 + mt * 16 + gid;
#pragma unroll
            for (int nt = 0; nt < 4; nt++) {
                int c = bn + warp_n * 32 + nt * 8 + 2 * tig;
                *(uint32_t*)&C[(size_t)r0 * D_MODEL + c] =
                    pack2(acc[mt][nt][0], acc[mt][nt][1]);
                *(uint32_t*)&C[(size_t)(r0 + 8) * D_MODEL + c] =
                    pack2(acc[mt][nt][2], acc[mt][nt][3]);
            }
        }
    }
}

// Output projection: fp16 A (g_oh) x fp16 W -> fp32 out
__global__ __launch_bounds__(256, 2)
void gemm_wo(float* __restrict__ C)
{
    __shared__ __align__(16) uint32_t As[2 * 1536];
    __shared__ __align__(16) uint32_t Bs[2 * 1536];

    const int bn = blockIdx.x * 128;
    const int bm = blockIdx.y * 128;

    float acc[4][4][4];
#pragma unroll
    for (int i = 0; i < 4; i++)
#pragma unroll
        for (int j = 0; j < 4; j++)
#pragma unroll
            for (int v = 0; v < 4; v++) acc[i][j][v] = 0.0f;

    gemm_mainloop(g_oh, g_woh, bm, bn, As, Bs, acc);

    const int lane = threadIdx.x & 31;
    const int warp = threadIdx.x >> 5;
    const int gid = lane >> 2;
    const int tig = lane & 3;
    const int warp_m = warp >> 2;
    const int warp_n = warp & 3;

#pragma unroll
    for (int mt = 0; mt < 4; mt++) {
        int r0 = bm + warp_m * 64 + mt * 16 + gid;
#pragma unroll
        for (int nt = 0; nt < 4; nt++) {
            int c = bn + warp_n * 32 + nt * 8 + 2 * tig;
            *(float2*)&C[(size_t)r0 * D_MODEL + c] =
                make_float2(acc[mt][nt][0], acc[mt][nt][1]);
            *(float2*)&C[(size_t)(r0 + 8) * D_MODEL + c] =
                make_float2(acc[mt][nt][2], acc[mt][nt][3]);
        }
    }
}

// ---------------------------------------------------------------------------
// Flash attention, fp16 I/O end-to-end. Br=128, Bc=32, dk=64, causal.
// Q pre-scaled (wq folded 1/sqrt(dk)); K/V smem fill is a raw uint4 copy.
// ---------------------------------------------------------------------------
__global__ __launch_bounds__(256, 2)
void attn_f16(const int* __restrict__ dummy)
{
    __shared__ __align__(16) uint32_t Ks[32 * 36];   // [k][d] fp16, 36 words/row
    __shared__ __align__(16) uint32_t Vs[32 * 36];

    const int tid = threadIdx.x;
    const int warp = tid >> 5;
    const int lane = tid & 31;
    const int gid = lane >> 2;
    const int tig = lane & 3;

    const int qt = (int)gridDim.x - 1 - (int)blockIdx.x;  // heavy blocks first
    const int bh = blockIdx.y;
    const int q0 = qt * 128;
    const size_t base = (size_t)(bh >> 4) * SEQ * D_MODEL + (size_t)(bh & 15) * D_K;

    const int qw = q0 + warp * 16;
    const int rowmax = qw + 15;

    const int l = lane;
    const uint32_t k_base = smem_u32(Ks) +
        (uint32_t)(((l & 7) + 8 * ((l >> 4) & 1)) * 36 + 4 * ((l >> 3) & 1)) * 4;
    const uint32_t v_base = smem_u32(Vs) +
        (uint32_t)(((l & 7) + 8 * ((l >> 3) & 1)) * 36 + 4 * ((l >> 4) & 1)) * 4;

    // Q fragments: direct fp16 loads (pre-scaled in projection)
    uint32_t qa[4][4];
    {
        const __half* Qr0 = g_qh + base + (size_t)(qw + gid) * D_MODEL;
        const __half* Qr1 = Qr0 + 8 * D_MODEL;
#pragma unroll
        for (int ks = 0; ks < 4; ks++) {
            qa[ks][0] = *(const uint32_t*)&Qr0[ks * 16 + 2 * tig];
            qa[ks][1] = *(const uint32_t*)&Qr1[ks * 16 + 2 * tig];
            qa[ks][2] = *(const uint32_t*)&Qr0[ks * 16 + 2 * tig + 8];
            qa[ks][3] = *(const uint32_t*)&Qr1[ks * 16 + 2 * tig + 8];
        }
    }

    float of[8][4];
#pragma unroll
    for (int i = 0; i < 8; i++)
#pragma unroll
        for (int j = 0; j < 4; j++) of[i][j] = 0.0f;
    float m0 = -1e30f, m1 = -1e30f, l0 = 0.0f, l1 = 0.0f;

    const int kr = tid >> 3;
    const int d8 = tid & 7;
    const int kv_sts = kr * 36 + d8 * 4;

    const int nkb = (q0 + 128) / 32;

    for (int kb = 0; kb < nkb; kb++) {
        const int k0 = kb * 32;
        {
            const uint4* Kr = (const uint4*)(g_kh + base + (size_t)(k0 + kr) * D_MODEL);
            const uint4* Vr = (const uint4*)(g_vh + base + (size_t)(k0 + kr) * D_MODEL);
            *(uint4*)&Ks[kv_sts] = Kr[d8];
            *(uint4*)&Vs[kv_sts] = Vr[d8];
        }
        __syncthreads();

        if (k0 <= rowmax) {
            float sc[4][4];
#pragma unroll
            for (int nt = 0; nt < 4; nt++)
#pragma unroll
                for (int v = 0; v < 4; v++) sc[nt][v] = 0.0f;
#pragma unroll
            for (int ks = 0; ks < 4; ks++) {
                uint32_t kb0[4], kb1[4];
                ldm4(kb0, k_base + (uint32_t)ks * 32u);
                ldm4(kb1, k_base + 2304u + (uint32_t)ks * 32u);
                mma_f16(sc[0], qa[ks][0], qa[ks][1], qa[ks][2], qa[ks][3],
                        kb0[0], kb0[1]);
                mma_f16(sc[1], qa[ks][0], qa[ks][1], qa[ks][2], qa[ks][3],
                        kb0[2], kb0[3]);
                mma_f16(sc[2], qa[ks][0], qa[ks][1], qa[ks][2], qa[ks][3],
                        kb1[0], kb1[1]);
                mma_f16(sc[3], qa[ks][0], qa[ks][1], qa[ks][2], qa[ks][3],
                        kb1[2], kb1[3]);
            }

            if (k0 + 31 > qw) {
                int r0g = qw + gid;
                int r1g = r0g + 8;
#pragma unroll
                for (int nt = 0; nt < 4; nt++) {
                    int c = k0 + nt * 8 + 2 * tig;
                    if (c > r0g)     sc[nt][0] = -1e30f;
                    if (c + 1 > r0g) sc[nt][1] = -1e30f;
                    if (c > r1g)     sc[nt][2] = -1e30f;
                    if (c + 1 > r1g) sc[nt][3] = -1e30f;
                }
            }

            float mx0 = sc[0][0], mx1 = sc[0][2];
#pragma unroll
            for (int nt = 0; nt < 4; nt++) {
                mx0 = fmaxf(mx0, fmaxf(sc[nt][0], sc[nt][1]));
                mx1 = fmaxf(mx1, fmaxf(sc[nt][2], sc[nt][3]));
            }
            mx0 = fmaxf(mx0, __shfl_xor_sync(0xffffffffu, mx0, 1));
            mx0 = fmaxf(mx0, __shfl_xor_sync(0xffffffffu, mx0, 2));
            mx1 = fmaxf(mx1, __shfl_xor_sync(0xffffffffu, mx1, 1));
            mx1 = fmaxf(mx1, __shfl_xor_sync(0xffffffffu, mx1, 2));

            float mn0 = fmaxf(m0, mx0);
            float mn1 = fmaxf(m1, mx1);
            float al0 = __expf(m0 - mn0);
            float al1 = __expf(m1 - mn1);
            m0 = mn0; m1 = mn1;

            float sum0 = 0.0f, sum1 = 0.0f;
#pragma unroll
            for (int nt = 0; nt < 4; nt++) {
                sc[nt][0] = __expf(sc[nt][0] - mn0);
                sc[nt][1] = __expf(sc[nt][1] - mn0);
                sc[nt][2] = __expf(sc[nt][2] - mn1);
                sc[nt][3] = __expf(sc[nt][3] - mn1);
                sum0 += sc[nt][0] + sc[nt][1];
                sum1 += sc[nt][2] + sc[nt][3];
            }
            sum0 += __shfl_xor_sync(0xffffffffu, sum0, 1);
            sum0 += __shfl_xor_sync(0xffffffffu, sum0, 2);
            sum1 += __shfl_xor_sync(0xffffffffu, sum1, 1);
            sum1 += __shfl_xor_sync(0xffffffffu, sum1, 2);
            l0 = l0 * al0 + sum0;
            l1 = l1 * al1 + sum1;

#pragma unroll
            for (int nt = 0; nt < 8; nt++) {
                of[nt][0] *= al0; of[nt][1] *= al0;
                of[nt][2] *= al1; of[nt][3] *= al1;
            }

            uint32_t pa[2][4];
#pragma unroll
            for (int s = 0; s < 2; s++) {
                pa[s][0] = pack2(sc[2 * s][0], sc[2 * s][1]);
                pa[s][1] = pack2(sc[2 * s][2], sc[2 * s][3]);
                pa[s][2] = pack2(sc[2 * s + 1][0], sc[2 * s + 1][1]);
                pa[s][3] = pack2(sc[2 * s + 1][2], sc[2 * s + 1][3]);
            }

#pragma unroll
            for (int s = 0; s < 2; s++) {
#pragma unroll
                for (int dp = 0; dp < 4; dp++) {
                    uint32_t vb[4];
                    ldm4t(vb, v_base + (uint32_t)s * 2304u + (uint32_t)dp * 32u);
                    mma_f16(of[dp * 2], pa[s][0], pa[s][1], pa[s][2], pa[s][3],
                            vb[0], vb[1]);
                    mma_f16(of[dp * 2 + 1], pa[s][0], pa[s][1], pa[s][2], pa[s][3],
                            vb[2], vb[3]);
                }
            }
        }
        __syncthreads();
    }

    // normalize + write fp16 O
    {
        float inv0 = 1.0f / l0;
        float inv1 = 1.0f / l1;
        __half* O0 = g_oh + base + (size_t)(qw + gid) * D_MODEL;
        __half* O1 = O0 + 8 * D_MODEL;
#pragma unroll
        for (int nt = 0; nt < 8; nt++) {
            int c = nt * 8 + 2 * tig;
            *(uint32_t*)&O0[c] = pack2(of[nt][0] * inv0, of[nt][1] * inv0);
            *(uint32_t*)&O1[c] = pack2(of[nt][2] * inv1, of[nt][3] * inv1);
        }
    }
}

// ---------------------------------------------------------------------------
extern "C" void kernel_launch(void* const* d_in, const int* in_sizes, int n_in,
                              void* d_out, int out_size)
{
    const float* x  = (const float*)d_in[0];
    const float* wq = (const float*)d_in[1];
    const float* wk = (const float*)d_in[2];
    const float* wv = (const float*)d_in[3];
    const float* wo = (const float*)d_in[4];
    const int* tok  = (const int*)d_in[5];
    float* out = (float*)d_out;

    to_half<<<2048, 256>>>((const float4*)x, (const float4*)wq,
                           (const float4*)wk, (const float4*)wv,
                           (const float4*)wo);

    dim3 gq(24, MTOT / 128);   // fused QKV
    gemm_qkv<<<gq, 256>>>(tok);

    dim3 ga(SEQ / 128, BATCH * NUM_HEADS);
    attn_f16<<<ga, 256>>>(tok);

    dim3 gw(D_MODEL / 128, MTOT / 128);
    gemm_wo<<<gw, 256>>>(out);
}

// round 8
// speedup vs baseline: 2.9129x; 1.2631x over previous
#include <cuda_runtime.h>
#include <cuda_fp16.h>
#include <math.h>
#include <stdint.h>

#define D_MODEL 1024
#define NUM_HEADS 16
#define SEQ 2048
#define BATCH 4
#define D_K 64
#define MTOT (BATCH * SEQ)   // 8192

// fp16 scratch (static device globals; no runtime allocation allowed)
__device__ __align__(16) __half g_xh[MTOT * D_MODEL];
__device__ __align__(16) __half g_qh[MTOT * D_MODEL];
__device__ __align__(16) __half g_kh[MTOT * D_MODEL];
__device__ __align__(16) __half g_vh[MTOT * D_MODEL];
__device__ __align__(16) __half g_oh[MTOT * D_MODEL];
__device__ __align__(16) __half g_wqh[D_MODEL * D_MODEL];
__device__ __align__(16) __half g_wkh[D_MODEL * D_MODEL];
__device__ __align__(16) __half g_wvh[D_MODEL * D_MODEL];
__device__ __align__(16) __half g_woh[D_MODEL * D_MODEL];

// ---------------------------------------------------------------------------
// helpers
// ---------------------------------------------------------------------------
__device__ __forceinline__ uint32_t pack2(float lo, float hi) {
    uint32_t r;
    asm("cvt.rn.f16x2.f32 %0, %1, %2;" : "=r"(r) : "f"(hi), "f"(lo));
    return r;
}

__device__ __forceinline__ void mma_f16(float c[4], uint32_t a0, uint32_t a1,
                                        uint32_t a2, uint32_t a3,
                                        uint32_t b0, uint32_t b1) {
    asm volatile(
        "mma.sync.aligned.m16n8k16.row.col.f32.f16.f16.f32 "
        "{%0,%1,%2,%3},{%4,%5,%6,%7},{%8,%9},{%0,%1,%2,%3};"
        : "+f"(c[0]), "+f"(c[1]), "+f"(c[2]), "+f"(c[3])
        : "r"(a0), "r"(a1), "r"(a2), "r"(a3), "r"(b0), "r"(b1));
}

__device__ __forceinline__ void ldm4(uint32_t (&r)[4], uint32_t addr) {
    asm volatile("ldmatrix.sync.aligned.m8n8.x4.shared.b16 {%0,%1,%2,%3}, [%4];"
                 : "=r"(r[0]), "=r"(r[1]), "=r"(r[2]), "=r"(r[3]) : "r"(addr));
}
__device__ __forceinline__ void ldm4t(uint32_t (&r)[4], uint32_t addr) {
    asm volatile("ldmatrix.sync.aligned.m8n8.x4.trans.shared.b16 {%0,%1,%2,%3}, [%4];"
                 : "=r"(r[0]), "=r"(r[1]), "=r"(r[2]), "=r"(r[3]) : "r"(addr));
}

__device__ __forceinline__ uint32_t smem_u32(const void* p) {
    return (uint32_t)__cvta_generic_to_shared(p);
}

__device__ __forceinline__ void cpa(uint32_t dst, const void* src) {
    asm volatile("cp.async.cg.shared.global [%0], [%1], 16;"
                 :: "r"(dst), "l"(src) : "memory");
}
__device__ __forceinline__ void cpa_commit() {
    asm volatile("cp.async.commit_group;" ::: "memory");
}
__device__ __forceinline__ void cpa_wait1() {
    asm volatile("cp.async.wait_group 1;" ::: "memory");
}
__device__ __forceinline__ void cpa_wait0() {
    asm volatile("cp.async.wait_group 0;" ::: "memory");
}

// ---------------------------------------------------------------------------
// fp32 -> fp16 pre-pass: x, and the 4 weights (wq scaled by 1/sqrt(dk)=0.125)
// ---------------------------------------------------------------------------
__global__ void to_half(const float4* __restrict__ x, const float4* __restrict__ wq,
                        const float4* __restrict__ wk, const float4* __restrict__ wv,
                        const float4* __restrict__ wo)
{
    const int NX = MTOT * D_MODEL / 4;
    const int NW = D_MODEL * D_MODEL / 4;
    const int stride = gridDim.x * blockDim.x;
    uint2* xh = (uint2*)g_xh;
    uint2* wqh = (uint2*)g_wqh;
    uint2* wkh = (uint2*)g_wkh;
    uint2* wvh = (uint2*)g_wvh;
    uint2* woh = (uint2*)g_woh;

    for (int i = blockIdx.x * blockDim.x + threadIdx.x; i < NX; i += stride) {
        float4 v = x[i];
        xh[i] = make_uint2(pack2(v.x, v.y), pack2(v.z, v.w));
    }
    for (int i = blockIdx.x * blockDim.x + threadIdx.x; i < NW; i += stride) {
        float4 a = wq[i];
        wqh[i] = make_uint2(pack2(a.x * 0.125f, a.y * 0.125f),
                            pack2(a.z * 0.125f, a.w * 0.125f));
        float4 b = wk[i];
        wkh[i] = make_uint2(pack2(b.x, b.y), pack2(b.z, b.w));
        float4 c = wv[i];
        wvh[i] = make_uint2(pack2(c.x, c.y), pack2(c.z, c.w));
        float4 d = wo[i];
        woh[i] = make_uint2(pack2(d.x, d.y), pack2(d.z, d.w));
    }
}

// ---------------------------------------------------------------------------
// GEMM: 128x128 block, 4 warps, warp tile 64x64, BK=64, cp.async double-buffer.
// smem rows: 64 fp16 = 128B + 16B pad = 144B (odd*16B mod 128 -> ldmatrix
// conflict-free; 8 threads/row STS hits 8 distinct bank groups).
// ---------------------------------------------------------------------------
#define GROW 144u                 // bytes per smem row
#define GOP (128u * GROW)         // bytes per operand tile (18432)
#define GSTAGE (2u * GOP)         // A+B per stage (36864)
#define GSMEM (2u * GSTAGE)       // double buffered (73728)
#define NKT (D_MODEL / 64)        // 16

__device__ __forceinline__ void gemm_mainloop(
    const __half* __restrict__ A, const __half* __restrict__ B,
    int bm, int bn, uint32_t sbase, float (&acc)[4][8][4])
{
    const int tid = threadIdx.x;
    const int lane = tid & 31;
    const int warp = tid >> 5;
    const int warp_m = warp >> 1;    // 0..1
    const int warp_n = warp & 1;     // 0..1

    const int r0 = tid >> 3;         // 0..15
    const int d = tid & 7;           // uint4 col within 64-wide k chunk

    const uint4* Au4 = (const uint4*)(A + (size_t)bm * D_MODEL);
    const uint4* Bu4 = (const uint4*)(B + (size_t)bn * D_MODEL);

    const int l = lane;
    const uint32_t a_base =
        (uint32_t)(warp_m * 64 + (l & 7) + 8 * ((l >> 3) & 1)) * GROW +
        ((l >> 4) & 1) * 16u;
    const uint32_t b_base =
        (uint32_t)(warp_n * 64 + (l & 7) + 8 * ((l >> 4) & 1)) * GROW +
        ((l >> 3) & 1) * 16u;

    // prologue: stage 0
    {
        uint32_t as_ = sbase, bs_ = sbase + GOP;
#pragma unroll
        for (int i = 0; i < 8; i++) {
            int row = r0 + 16 * i;
            cpa(as_ + row * GROW + d * 16, Au4 + row * 128 + d);
            cpa(bs_ + row * GROW + d * 16, Bu4 + row * 128 + d);
        }
        cpa_commit();
    }

    for (int kt = 0; kt < NKT; kt++) {
        const uint32_t buf = (uint32_t)(kt & 1);
        if (kt + 1 < NKT) {
            uint32_t as_ = sbase + (buf ^ 1) * GSTAGE;
            uint32_t bs_ = as_ + GOP;
#pragma unroll
            for (int i = 0; i < 8; i++) {
                int row = r0 + 16 * i;
                cpa(as_ + row * GROW + d * 16, Au4 + row * 128 + (kt + 1) * 8 + d);
                cpa(bs_ + row * GROW + d * 16, Bu4 + row * 128 + (kt + 1) * 8 + d);
            }
            cpa_commit();
            cpa_wait1();
        } else {
            cpa_wait0();
        }
        __syncthreads();

        const uint32_t aS = sbase + buf * GSTAGE;
        const uint32_t bS = aS + GOP;
#pragma unroll
        for (int g = 0; g < 4; g++) {
            uint32_t af[4][4], bf[4][4];
#pragma unroll
            for (int mt = 0; mt < 4; mt++)
                ldm4(af[mt], aS + a_base + (uint32_t)mt * 2304u + (uint32_t)g * 32u);
#pragma unroll
            for (int p = 0; p < 4; p++)
                ldm4(bf[p], bS + b_base + (uint32_t)p * 2304u + (uint32_t)g * 32u);
#pragma unroll
            for (int mt = 0; mt < 4; mt++)
#pragma unroll
                for (int nt = 0; nt < 8; nt++)
                    mma_f16(acc[mt][nt], af[mt][0], af[mt][1], af[mt][2], af[mt][3],
                            bf[nt >> 1][(nt & 1) * 2], bf[nt >> 1][(nt & 1) * 2 + 1]);
        }
        __syncthreads();
    }
}

// Fused QKV projection: grid (24, 64). blockIdx.x>>3 selects matrix (q/k/v),
// fp16 output, RoPE applied for q and k.
__global__ __launch_bounds__(128)
void gemm_qkv(const int* __restrict__ pos)
{
    extern __shared__ __align__(16) uint32_t dsm[];
    const uint32_t sbase = smem_u32(dsm);

    const int mat = blockIdx.x >> 3;
    const int bn = (blockIdx.x & 7) * 128;
    const int bm = blockIdx.y * 128;

    const __half* B = (mat == 0) ? g_wqh : (mat == 1) ? g_wkh : g_wvh;
    __half* C = (mat == 0) ? g_qh : (mat == 1) ? g_kh : g_vh;
    const int rope = (mat < 2);

    float acc[4][8][4];
#pragma unroll
    for (int i = 0; i < 4; i++)
#pragma unroll
        for (int j = 0; j < 8; j++)
#pragma unroll
            for (int v = 0; v < 4; v++) acc[i][j][v] = 0.0f;

    gemm_mainloop(g_xh, B, bm, bn, sbase, acc);

    const int lane = threadIdx.x & 31;
    const int warp = threadIdx.x >> 5;
    const int gid = lane >> 2;
    const int tig = lane & 3;
    const int warp_m = warp >> 1;
    const int warp_n = warp & 1;

    if (rope) {
        const float lg = logf(10000.0f);
#pragma unroll
        for (int mt = 0; mt < 4; mt++) {
            int r0 = bm + warp_m * 64 + mt * 16 + gid;
            float p0 = (float)pos[r0 & (SEQ - 1)];
            float p1 = (float)pos[(r0 + 8) & (SEQ - 1)];
#pragma unroll
            for (int nt = 0; nt < 8; nt++) {
                int c = bn + warp_n * 64 + nt * 8 + 2 * tig;
                int dd = c & (D_K - 1);
                float invf = expf(-lg * ((float)dd / (float)D_K));
                float sn0, cs0, sn1, cs1;
                sincosf(p0 * invf, &sn0, &cs0);
                sincosf(p1 * invf, &sn1, &cs1);
                float v0 = acc[mt][nt][0], v1 = acc[mt][nt][1];
                float w0 = acc[mt][nt][2], w1 = acc[mt][nt][3];
                *(uint32_t*)&C[(size_t)r0 * D_MODEL + c] =
                    pack2(v0 * cs0 - v1 * sn0, v0 * sn0 + v1 * cs0);
                *(uint32_t*)&C[(size_t)(r0 + 8) * D_MODEL + c] =
                    pack2(w0 * cs1 - w1 * sn1, w0 * sn1 + w1 * cs1);
            }
        }
    } else {
#pragma unroll
        for (int mt = 0; mt < 4; mt++) {
            int r0 = bm + warp_m * 64 + mt * 16 + gid;
#pragma unroll
            for (int nt = 0; nt < 8; nt++) {
                int c = bn + warp_n * 64 + nt * 8 + 2 * tig;
                *(uint32_t*)&C[(size_t)r0 * D_MODEL + c] =
                    pack2(acc[mt][nt][0], acc[mt][nt][1]);
                *(uint32_t*)&C[(size_t)(r0 + 8) * D_MODEL + c] =
                    pack2(acc[mt][nt][2], acc[mt][nt][3]);
            }
        }
    }
}

// Output projection: fp16 A (g_oh) x fp16 W -> fp32 out
__global__ __launch_bounds__(128)
void gemm_wo(float* __restrict__ C)
{
    extern __shared__ __align__(16) uint32_t dsm[];
    const uint32_t sbase = smem_u32(dsm);

    const int bn = blockIdx.x * 128;
    const int bm = blockIdx.y * 128;

    float acc[4][8][4];
#pragma unroll
    for (int i = 0; i < 4; i++)
#pragma unroll
        for (int j = 0; j < 8; j++)
#pragma unroll
            for (int v = 0; v < 4; v++) acc[i][j][v] = 0.0f;

    gemm_mainloop(g_oh, g_woh, bm, bn, sbase, acc);

    const int lane = threadIdx.x & 31;
    const int warp = threadIdx.x >> 5;
    const int gid = lane >> 2;
    const int tig = lane & 3;
    const int warp_m = warp >> 1;
    const int warp_n = warp & 1;

#pragma unroll
    for (int mt = 0; mt < 4; mt++) {
        int r0 = bm + warp_m * 64 + mt * 16 + gid;
#pragma unroll
        for (int nt = 0; nt < 8; nt++) {
            int c = bn + warp_n * 64 + nt * 8 + 2 * tig;
            *(float2*)&C[(size_t)r0 * D_MODEL + c] =
                make_float2(acc[mt][nt][0], acc[mt][nt][1]);
            *(float2*)&C[(size_t)(r0 + 8) * D_MODEL + c] =
                make_float2(acc[mt][nt][2], acc[mt][nt][3]);
        }
    }
}

// ---------------------------------------------------------------------------
// Flash attention, fp16 I/O. Br=128, Bc=32, dk=64, causal.
// 4 warps x 32 q rows; Q frags in registers; K ldm / V ldm-trans shared
// across both m-atoms (8 ldm per 32 mma in both phases).
// ---------------------------------------------------------------------------
__global__ __launch_bounds__(128)
void attn_f16()
{
    __shared__ __align__(16) uint32_t Ks[32 * 36];   // [k][d] fp16, 36 words/row
    __shared__ __align__(16) uint32_t Vs[32 * 36];

    const int tid = threadIdx.x;
    const int warp = tid >> 5;
    const int lane = tid & 31;
    const int gid = lane >> 2;
    const int tig = lane & 3;

    const int qt = (int)gridDim.x - 1 - (int)blockIdx.x;  // heavy blocks first
    const int bh = blockIdx.y;
    const int q0 = qt * 128;
    const size_t base = (size_t)(bh >> 4) * SEQ * D_MODEL + (size_t)(bh & 15) * D_K;

    const int qw = q0 + warp * 32;
    const int rowmax = qw + 31;

    const int l = lane;
    const uint32_t k_base = smem_u32(Ks) +
        (uint32_t)(((l & 7) + 8 * ((l >> 4) & 1)) * 36 + 4 * ((l >> 3) & 1)) * 4;
    const uint32_t v_base = smem_u32(Vs) +
        (uint32_t)(((l & 7) + 8 * ((l >> 3) & 1)) * 36 + 4 * ((l >> 4) & 1)) * 4;

    // Q fragments: 2 m-atoms x 4 k16-steps (pre-scaled in projection)
    uint32_t qa[4][8];
#pragma unroll
    for (int ma = 0; ma < 2; ma++) {
        const __half* Qr0 = g_qh + base + (size_t)(qw + ma * 16 + gid) * D_MODEL;
        const __half* Qr1 = Qr0 + 8 * D_MODEL;
#pragma unroll
        for (int ks = 0; ks < 4; ks++) {
            qa[ks][ma * 4 + 0] = *(const uint32_t*)&Qr0[ks * 16 + 2 * tig];
            qa[ks][ma * 4 + 1] = *(const uint32_t*)&Qr1[ks * 16 + 2 * tig];
            qa[ks][ma * 4 + 2] = *(const uint32_t*)&Qr0[ks * 16 + 2 * tig + 8];
            qa[ks][ma * 4 + 3] = *(const uint32_t*)&Qr1[ks * 16 + 2 * tig + 8];
        }
    }

    float of[2][8][4];
#pragma unroll
    for (int ma = 0; ma < 2; ma++)
#pragma unroll
        for (int i = 0; i < 8; i++)
#pragma unroll
            for (int j = 0; j < 4; j++) of[ma][i][j] = 0.0f;
    float mm[2][2] = {{-1e30f, -1e30f}, {-1e30f, -1e30f}};
    float ll[2][2] = {{0.0f, 0.0f}, {0.0f, 0.0f}};

    const int kr = tid >> 3;          // 0..15
    const int d8 = tid & 7;
    const int sts0 = kr * 36 + d8 * 4;
    const int sts1 = (kr + 16) * 36 + d8 * 4;

    const int nkb = (q0 + 128) / 32;

    for (int kb = 0; kb < nkb; kb++) {
        const int k0 = kb * 32;
        {
            const uint4* Kr0 = (const uint4*)(g_kh + base + (size_t)(k0 + kr) * D_MODEL);
            const uint4* Kr1 = (const uint4*)(g_kh + base + (size_t)(k0 + kr + 16) * D_MODEL);
            const uint4* Vr0 = (const uint4*)(g_vh + base + (size_t)(k0 + kr) * D_MODEL);
            const uint4* Vr1 = (const uint4*)(g_vh + base + (size_t)(k0 + kr + 16) * D_MODEL);
            *(uint4*)&Ks[sts0] = Kr0[d8];
            *(uint4*)&Ks[sts1] = Kr1[d8];
            *(uint4*)&Vs[sts0] = Vr0[d8];
            *(uint4*)&Vs[sts1] = Vr1[d8];
        }
        __syncthreads();

        if (k0 <= rowmax) {
            // S = Q K^T : 2 m-atoms x 4 n-atoms, 4 k16-steps
            float sc[2][4][4];
#pragma unroll
            for (int ma = 0; ma < 2; ma++)
#pragma unroll
                for (int nt = 0; nt < 4; nt++)
#pragma unroll
                    for (int v = 0; v < 4; v++) sc[ma][nt][v] = 0.0f;
#pragma unroll
            for (int ks = 0; ks < 4; ks++) {
                uint32_t kb0[4], kb1[4];
                ldm4(kb0, k_base + (uint32_t)ks * 32u);            // kc 0-15
                ldm4(kb1, k_base + 2304u + (uint32_t)ks * 32u);    // kc 16-31
#pragma unroll
                for (int ma = 0; ma < 2; ma++) {
                    mma_f16(sc[ma][0], qa[ks][ma*4+0], qa[ks][ma*4+1],
                            qa[ks][ma*4+2], qa[ks][ma*4+3], kb0[0], kb0[1]);
                    mma_f16(sc[ma][1], qa[ks][ma*4+0], qa[ks][ma*4+1],
                            qa[ks][ma*4+2], qa[ks][ma*4+3], kb0[2], kb0[3]);
                    mma_f16(sc[ma][2], qa[ks][ma*4+0], qa[ks][ma*4+1],
                            qa[ks][ma*4+2], qa[ks][ma*4+3], kb1[0], kb1[1]);
                    mma_f16(sc[ma][3], qa[ks][ma*4+0], qa[ks][ma*4+1],
                            qa[ks][ma*4+2], qa[ks][ma*4+3], kb1[2], kb1[3]);
                }
            }

            // causal mask (diagonal-overlapping blocks only)
            if (k0 + 31 > qw) {
#pragma unroll
                for (int ma = 0; ma < 2; ma++) {
                    int r0g = qw + ma * 16 + gid;
                    int r1g = r0g + 8;
#pragma unroll
                    for (int nt = 0; nt < 4; nt++) {
                        int c = k0 + nt * 8 + 2 * tig;
                        if (c > r0g)     sc[ma][nt][0] = -1e30f;
                        if (c + 1 > r0g) sc[ma][nt][1] = -1e30f;
                        if (c > r1g)     sc[ma][nt][2] = -1e30f;
                        if (c + 1 > r1g) sc[ma][nt][3] = -1e30f;
                    }
                }
            }

            // online softmax per m-atom
            uint32_t pa[2][2][4];
#pragma unroll
            for (int ma = 0; ma < 2; ma++) {
                float mx0 = sc[ma][0][0], mx1 = sc[ma][0][2];
#pragma unroll
                for (int nt = 0; nt < 4; nt++) {
                    mx0 = fmaxf(mx0, fmaxf(sc[ma][nt][0], sc[ma][nt][1]));
                    mx1 = fmaxf(mx1, fmaxf(sc[ma][nt][2], sc[ma][nt][3]));
                }
                mx0 = fmaxf(mx0, __shfl_xor_sync(0xffffffffu, mx0, 1));
                mx0 = fmaxf(mx0, __shfl_xor_sync(0xffffffffu, mx0, 2));
                mx1 = fmaxf(mx1, __shfl_xor_sync(0xffffffffu, mx1, 1));
                mx1 = fmaxf(mx1, __shfl_xor_sync(0xffffffffu, mx1, 2));

                float mn0 = fmaxf(mm[ma][0], mx0);
                float mn1 = fmaxf(mm[ma][1], mx1);
                float al0 = __expf(mm[ma][0] - mn0);
                float al1 = __expf(mm[ma][1] - mn1);
                mm[ma][0] = mn0; mm[ma][1] = mn1;

                float sum0 = 0.0f, sum1 = 0.0f;
#pragma unroll
                for (int nt = 0; nt < 4; nt++) {
                    sc[ma][nt][0] = __expf(sc[ma][nt][0] - mn0);
                    sc[ma][nt][1] = __expf(sc[ma][nt][1] - mn0);
                    sc[ma][nt][2] = __expf(sc[ma][nt][2] - mn1);
                    sc[ma][nt][3] = __expf(sc[ma][nt][3] - mn1);
                    sum0 += sc[ma][nt][0] + sc[ma][nt][1];
                    sum1 += sc[ma][nt][2] + sc[ma][nt][3];
                }
                sum0 += __shfl_xor_sync(0xffffffffu, sum0, 1);
                sum0 += __shfl_xor_sync(0xffffffffu, sum0, 2);
                sum1 += __shfl_xor_sync(0xffffffffu, sum1, 1);
                sum1 += __shfl_xor_sync(0xffffffffu, sum1, 2);
                ll[ma][0] = ll[ma][0] * al0 + sum0;
                ll[ma][1] = ll[ma][1] * al1 + sum1;

#pragma unroll
                for (int nt = 0; nt < 8; nt++) {
                    of[ma][nt][0] *= al0; of[ma][nt][1] *= al0;
                    of[ma][nt][2] *= al1; of[ma][nt][3] *= al1;
                }

#pragma unroll
                for (int s = 0; s < 2; s++) {
                    pa[ma][s][0] = pack2(sc[ma][2*s][0], sc[ma][2*s][1]);
                    pa[ma][s][1] = pack2(sc[ma][2*s][2], sc[ma][2*s][3]);
                    pa[ma][s][2] = pack2(sc[ma][2*s+1][0], sc[ma][2*s+1][1]);
                    pa[ma][s][3] = pack2(sc[ma][2*s+1][2], sc[ma][2*s+1][3]);
                }
            }

            // O += P @ V : V ldm shared across both m-atoms
#pragma unroll
            for (int s = 0; s < 2; s++) {
#pragma unroll
                for (int dp = 0; dp < 4; dp++) {
                    uint32_t vb[4];
                    ldm4t(vb, v_base + (uint32_t)s * 2304u + (uint32_t)dp * 32u);
#pragma unroll
                    for (int ma = 0; ma < 2; ma++) {
                        mma_f16(of[ma][dp * 2], pa[ma][s][0], pa[ma][s][1],
                                pa[ma][s][2], pa[ma][s][3], vb[0], vb[1]);
                        mma_f16(of[ma][dp * 2 + 1], pa[ma][s][0], pa[ma][s][1],
                                pa[ma][s][2], pa[ma][s][3], vb[2], vb[3]);
                    }
                }
            }
        }
        __syncthreads();
    }

    // normalize + write fp16 O
#pragma unroll
    for (int ma = 0; ma < 2; ma++) {
        float inv0 = 1.0f / ll[ma][0];
        float inv1 = 1.0f / ll[ma][1];
        __half* O0 = g_oh + base + (size_t)(qw + ma * 16 + gid) * D_MODEL;
        __half* O1 = O0 + 8 * D_MODEL;
#pragma unroll
        for (int nt = 0; nt < 8; nt++) {
            int c = nt * 8 + 2 * tig;
            *(uint32_t*)&O0[c] = pack2(of[ma][nt][0] * inv0, of[ma][nt][1] * inv0);
            *(uint32_t*)&O1[c] = pack2(of[ma][nt][2] * inv1, of[ma][nt][3] * inv1);
        }
    }
}

// ---------------------------------------------------------------------------
extern "C" void kernel_launch(void* const* d_in, const int* in_sizes, int n_in,
                              void* d_out, int out_size)
{
    const float* x  = (const float*)d_in[0];
    const float* wq = (const float*)d_in[1];
    const float* wk = (const float*)d_in[2];
    const float* wv = (const float*)d_in[3];
    const float* wo = (const float*)d_in[4];
    const int* tok  = (const int*)d_in[5];
    float* out = (float*)d_out;

    cudaFuncSetAttribute(gemm_qkv, cudaFuncAttributeMaxDynamicSharedMemorySize, GSMEM);
    cudaFuncSetAttribute(gemm_wo, cudaFuncAttributeMaxDynamicSharedMemorySize, GSMEM);

    to_half<<<2048, 256>>>((const float4*)x, (const float4*)wq,
                           (const float4*)wk, (const float4*)wv,
                           (const float4*)wo);

    dim3 gq(24, MTOT / 128);   // fused QKV
    gemm_qkv<<<gq, 128, GSMEM>>>(tok);

    dim3 ga(SEQ / 128, BATCH * NUM_HEADS);
    attn_f16<<<ga, 128>>>();

    dim3 gw(D_MODEL / 128, MTOT / 128);
    gemm_wo<<<gw, 128, GSMEM>>>(out);
}

// round 10
// speedup vs baseline: 3.3925x; 1.1647x over previous
#include <cuda_runtime.h>
#include <cuda_fp16.h>
#include <math.h>
#include <stdint.h>

#define D_MODEL 1024
#define NUM_HEADS 16
#define SEQ 2048
#define BATCH 4
#define D_K 64
#define MTOT (BATCH * SEQ)   // 8192

// fp16 scratch (static device globals; no runtime allocation allowed)
__device__ __align__(16) __half g_xh[MTOT * D_MODEL];
__device__ __align__(16) __half g_qh[MTOT * D_MODEL];
__device__ __align__(16) __half g_kh[MTOT * D_MODEL];
__device__ __align__(16) __half g_vh[MTOT * D_MODEL];
__device__ __align__(16) __half g_oh[MTOT * D_MODEL];
__device__ __align__(16) __half g_wqh[D_MODEL * D_MODEL];
__device__ __align__(16) __half g_wkh[D_MODEL * D_MODEL];
__device__ __align__(16) __half g_wvh[D_MODEL * D_MODEL];
__device__ __align__(16) __half g_woh[D_MODEL * D_MODEL];
__device__ __align__(16) float2 g_rope[SEQ * 32];   // (cos, sin) per (pos, j)

#define QSCALE (0.125f * 1.4426950408889634f)   // 1/sqrt(dk) * log2(e)

// ---------------------------------------------------------------------------
// helpers
// ---------------------------------------------------------------------------
__device__ __forceinline__ uint32_t pack2(float lo, float hi) {
    uint32_t r;
    asm("cvt.rn.f16x2.f32 %0, %1, %2;" : "=r"(r) : "f"(hi), "f"(lo));
    return r;
}

__device__ __forceinline__ float ex2(float x) {
    float r;
    asm("ex2.approx.ftz.f32 %0, %1;" : "=f"(r) : "f"(x));
    return r;
}

__device__ __forceinline__ void mma_f16(float c[4], uint32_t a0, uint32_t a1,
                                        uint32_t a2, uint32_t a3,
                                        uint32_t b0, uint32_t b1) {
    asm volatile(
        "mma.sync.aligned.m16n8k16.row.col.f32.f16.f16.f32 "
        "{%0,%1,%2,%3},{%4,%5,%6,%7},{%8,%9},{%0,%1,%2,%3};"
        : "+f"(c[0]), "+f"(c[1]), "+f"(c[2]), "+f"(c[3])
        : "r"(a0), "r"(a1), "r"(a2), "r"(a3), "r"(b0), "r"(b1));
}

__device__ __forceinline__ void ldm4(uint32_t (&r)[4], uint32_t addr) {
    asm volatile("ldmatrix.sync.aligned.m8n8.x4.shared.b16 {%0,%1,%2,%3}, [%4];"
                 : "=r"(r[0]), "=r"(r[1]), "=r"(r[2]), "=r"(r[3]) : "r"(addr));
}
__device__ __forceinline__ void ldm4t(uint32_t (&r)[4], uint32_t addr) {
    asm volatile("ldmatrix.sync.aligned.m8n8.x4.trans.shared.b16 {%0,%1,%2,%3}, [%4];"
                 : "=r"(r[0]), "=r"(r[1]), "=r"(r[2]), "=r"(r[3]) : "r"(addr));
}

__device__ __forceinline__ uint32_t smem_u32(const void* p) {
    return (uint32_t)__cvta_generic_to_shared(p);
}

__device__ __forceinline__ void cpa(uint32_t dst, const void* src) {
    asm volatile("cp.async.cg.shared.global [%0], [%1], 16;"
                 :: "r"(dst), "l"(src) : "memory");
}
__device__ __forceinline__ void cpa_commit() {
    asm volatile("cp.async.commit_group;" ::: "memory");
}
__device__ __forceinline__ void cpa_wait1() {
    asm volatile("cp.async.wait_group 1;" ::: "memory");
}
__device__ __forceinline__ void cpa_wait0() {
    asm volatile("cp.async.wait_group 0;" ::: "memory");
}

// ---------------------------------------------------------------------------
// pre-pass: fp16 conversions + RoPE table.
// wq folded with 1/sqrt(dk)*log2(e) (exp2-domain softmax).
// ---------------------------------------------------------------------------
__global__ void to_half(const float4* __restrict__ x, const float4* __restrict__ wq,
                        const float4* __restrict__ wk, const float4* __restrict__ wv,
                        const float4* __restrict__ wo, const int* __restrict__ pos)
{
    const int NX = MTOT * D_MODEL / 4;
    const int NW = D_MODEL * D_MODEL / 4;
    const int NR = SEQ * 32;
    const int stride = gridDim.x * blockDim.x;
    uint2* xh = (uint2*)g_xh;
    uint2* wqh = (uint2*)g_wqh;
    uint2* wkh = (uint2*)g_wkh;
    uint2* wvh = (uint2*)g_wvh;
    uint2* woh = (uint2*)g_woh;

    for (int i = blockIdx.x * blockDim.x + threadIdx.x; i < NX; i += stride) {
        float4 v = x[i];
        xh[i] = make_uint2(pack2(v.x, v.y), pack2(v.z, v.w));
    }
    for (int i = blockIdx.x * blockDim.x + threadIdx.x; i < NW; i += stride) {
        float4 a = wq[i];
        wqh[i] = make_uint2(pack2(a.x * QSCALE, a.y * QSCALE),
                            pack2(a.z * QSCALE, a.w * QSCALE));
        float4 b = wk[i];
        wkh[i] = make_uint2(pack2(b.x, b.y), pack2(b.z, b.w));
        float4 c = wv[i];
        wvh[i] = make_uint2(pack2(c.x, c.y), pack2(c.z, c.w));
        float4 d = wo[i];
        woh[i] = make_uint2(pack2(d.x, d.y), pack2(d.z, d.w));
    }
    const float lg = logf(10000.0f);
    for (int i = blockIdx.x * blockDim.x + threadIdx.x; i < NR; i += stride) {
        int s = i >> 5;
        int j = i & 31;
        float invf = expf(-lg * ((float)(2 * j) / (float)D_K));
        float sn, cs;
        sincosf((float)pos[s] * invf, &sn, &cs);
        g_rope[i] = make_float2(cs, sn);
    }
}

// ---------------------------------------------------------------------------
// GEMM: 128x128 block, 4 warps, warp tile 64x64, BK=64, cp.async double-buffer.
// (unchanged from round 8)
// ---------------------------------------------------------------------------
#define GROW 144u
#define GOP (128u * GROW)
#define GSTAGE (2u * GOP)
#define GSMEM (2u * GSTAGE)
#define NKT (D_MODEL / 64)

__device__ __forceinline__ void gemm_mainloop(
    const __half* __restrict__ A, const __half* __restrict__ B,
    int bm, int bn, uint32_t sbase, float (&acc)[4][8][4])
{
    const int tid = threadIdx.x;
    const int lane = tid & 31;
    const int warp = tid >> 5;
    const int warp_m = warp >> 1;
    const int warp_n = warp & 1;

    const int r0 = tid >> 3;
    const int d = tid & 7;

    const uint4* Au4 = (const uint4*)(A + (size_t)bm * D_MODEL);
    const uint4* Bu4 = (const uint4*)(B + (size_t)bn * D_MODEL);

    const int l = lane;
    const uint32_t a_base =
        (uint32_t)(warp_m * 64 + (l & 7) + 8 * ((l >> 3) & 1)) * GROW +
        ((l >> 4) & 1) * 16u;
    const uint32_t b_base =
        (uint32_t)(warp_n * 64 + (l & 7) + 8 * ((l >> 4) & 1)) * GROW +
        ((l >> 3) & 1) * 16u;

    {
        uint32_t as_ = sbase, bs_ = sbase + GOP;
#pragma unroll
        for (int i = 0; i < 8; i++) {
            int row = r0 + 16 * i;
            cpa(as_ + row * GROW + d * 16, Au4 + row * 128 + d);
            cpa(bs_ + row * GROW + d * 16, Bu4 + row * 128 + d);
        }
        cpa_commit();
    }

    for (int kt = 0; kt < NKT; kt++) {
        const uint32_t buf = (uint32_t)(kt & 1);
        if (kt + 1 < NKT) {
            uint32_t as_ = sbase + (buf ^ 1) * GSTAGE;
            uint32_t bs_ = as_ + GOP;
#pragma unroll
            for (int i = 0; i < 8; i++) {
                int row = r0 + 16 * i;
                cpa(as_ + row * GROW + d * 16, Au4 + row * 128 + (kt + 1) * 8 + d);
                cpa(bs_ + row * GROW + d * 16, Bu4 + row * 128 + (kt + 1) * 8 + d);
            }
            cpa_commit();
            cpa_wait1();
        } else {
            cpa_wait0();
        }
        __syncthreads();

        const uint32_t aS = sbase + buf * GSTAGE;
        const uint32_t bS = aS + GOP;
#pragma unroll
        for (int g = 0; g < 4; g++) {
            uint32_t af[4][4], bf[4][4];
#pragma unroll
            for (int mt = 0; mt < 4; mt++)
                ldm4(af[mt], aS + a_base + (uint32_t)mt * 2304u + (uint32_t)g * 32u);
#pragma unroll
            for (int p = 0; p < 4; p++)
                ldm4(bf[p], bS + b_base + (uint32_t)p * 2304u + (uint32_t)g * 32u);
#pragma unroll
            for (int mt = 0; mt < 4; mt++)
#pragma unroll
                for (int nt = 0; nt < 8; nt++)
                    mma_f16(acc[mt][nt], af[mt][0], af[mt][1], af[mt][2], af[mt][3],
                            bf[nt >> 1][(nt & 1) * 2], bf[nt >> 1][(nt & 1) * 2 + 1]);
        }
        __syncthreads();
    }
}

// Fused QKV projection; RoPE via precomputed table.
__global__ __launch_bounds__(128)
void gemm_qkv()
{
    extern __shared__ __align__(16) uint32_t dsm[];
    const uint32_t sbase = smem_u32(dsm);

    const int mat = blockIdx.x >> 3;
    const int bn = (blockIdx.x & 7) * 128;
    const int bm = blockIdx.y * 128;

    const __half* B = (mat == 0) ? g_wqh : (mat == 1) ? g_wkh : g_wvh;
    __half* C = (mat == 0) ? g_qh : (mat == 1) ? g_kh : g_vh;
    const int rope = (mat < 2);

    float acc[4][8][4];
#pragma unroll
    for (int i = 0; i < 4; i++)
#pragma unroll
        for (int j = 0; j < 8; j++)
#pragma unroll
            for (int v = 0; v < 4; v++) acc[i][j][v] = 0.0f;

    gemm_mainloop(g_xh, B, bm, bn, sbase, acc);

    const int lane = threadIdx.x & 31;
    const int warp = threadIdx.x >> 5;
    const int gid = lane >> 2;
    const int tig = lane & 3;
    const int warp_m = warp >> 1;
    const int warp_n = warp & 1;

    if (rope) {
#pragma unroll
        for (int mt = 0; mt < 4; mt++) {
            int r0 = bm + warp_m * 64 + mt * 16 + gid;
            int s0 = r0 & (SEQ - 1);
            int s1 = (r0 + 8) & (SEQ - 1);
#pragma unroll
            for (int nt = 0; nt < 8; nt++) {
                int c = bn + warp_n * 64 + nt * 8 + 2 * tig;
                int j = (c & (D_K - 1)) >> 1;
                float2 r0v = g_rope[s0 * 32 + j];
                float2 r1v = g_rope[s1 * 32 + j];
                float v0 = acc[mt][nt][0], v1 = acc[mt][nt][1];
                float w0 = acc[mt][nt][2], w1 = acc[mt][nt][3];
                *(uint32_t*)&C[(size_t)r0 * D_MODEL + c] =
                    pack2(v0 * r0v.x - v1 * r0v.y, v0 * r0v.y + v1 * r0v.x);
                *(uint32_t*)&C[(size_t)(r0 + 8) * D_MODEL + c] =
                    pack2(w0 * r1v.x - w1 * r1v.y, w0 * r1v.y + w1 * r1v.x);
            }
        }
    } else {
#pragma unroll
        for (int mt = 0; mt < 4; mt++) {
            int r0 = bm + warp_m * 64 + mt * 16 + gid;
#pragma unroll
            for (int nt = 0; nt < 8; nt++) {
                int c = bn + warp_n * 64 + nt * 8 + 2 * tig;
                *(uint32_t*)&C[(size_t)r0 * D_MODEL + c] =
                    pack2(acc[mt][nt][0], acc[mt][nt][1]);
                *(uint32_t*)&C[(size_t)(r0 + 8) * D_MODEL + c] =
                    pack2(acc[mt][nt][2], acc[mt][nt][3]);
            }
        }
    }
}

// Output projection: fp16 A (g_oh) x fp16 W -> fp32 out
__global__ __launch_bounds__(128)
void gemm_wo(float* __restrict__ C)
{
    extern __shared__ __align__(16) uint32_t dsm[];
    const uint32_t sbase = smem_u32(dsm);

    const int bn = blockIdx.x * 128;
    const int bm = blockIdx.y * 128;

    float acc[4][8][4];
#pragma unroll
    for (int i = 0; i < 4; i++)
#pragma unroll
        for (int j = 0; j < 8; j++)
#pragma unroll
            for (int v = 0; v < 4; v++) acc[i][j][v] = 0.0f;

    gemm_mainloop(g_oh, g_woh, bm, bn, sbase, acc);

    const int lane = threadIdx.x & 31;
    const int warp = threadIdx.x >> 5;
    const int gid = lane >> 2;
    const int tig = lane & 3;
    const int warp_m = warp >> 1;
    const int warp_n = warp & 1;

#pragma unroll
    for (int mt = 0; mt < 4; mt++) {
        int r0 = bm + warp_m * 64 + mt * 16 + gid;
#pragma unroll
        for (int nt = 0; nt < 8; nt++) {
            int c = bn + warp_n * 64 + nt * 8 + 2 * tig;
            *(float2*)&C[(size_t)r0 * D_MODEL + c] =
                make_float2(acc[mt][nt][0], acc[mt][nt][1]);
            *(float2*)&C[(size_t)(r0 + 8) * D_MODEL + c] =
                make_float2(acc[mt][nt][2], acc[mt][nt][3]);
        }
    }
}

// ---------------------------------------------------------------------------
// Flash attention: Br=128 (4 warps x 32 q), outer KV tiles of 64 keys in a
// 3-stage cp.async ring (ONE syncthreads per tile), two 32-key halves inside.
// exp2-domain softmax (scale*log2e folded into wq).
// Stage layout: K[64][36w] then V[64][36w]; 3 stages, 18432 B each.
// ---------------------------------------------------------------------------
#define AST 18432u               // bytes per stage
#define ASMEM (3u * AST)         // 55296

__global__ __launch_bounds__(128)
void attn_f16()
{
    extern __shared__ __align__(16) uint32_t asm_[];
    const uint32_t sb = smem_u32(asm_);

    const int tid = threadIdx.x;
    const int warp = tid >> 5;
    const int lane = tid & 31;
    const int gid = lane >> 2;
    const int tig = lane & 3;

    const int qt = (int)gridDim.x - 1 - (int)blockIdx.x;  // heavy blocks first
    const int bh = blockIdx.y;
    const int q0 = qt * 128;
    const size_t base = (size_t)(bh >> 4) * SEQ * D_MODEL + (size_t)(bh & 15) * D_K;

    const int qw = q0 + warp * 32;
    const int rowmax = qw + 31;

    const int l = lane;
    const uint32_t k_lane =
        (uint32_t)(((l & 7) + 8 * ((l >> 4) & 1)) * 36 + 4 * ((l >> 3) & 1)) * 4;
    const uint32_t v_lane = 9216u +
        (uint32_t)(((l & 7) + 8 * ((l >> 3) & 1)) * 36 + 4 * ((l >> 4) & 1)) * 4;

    // Q fragments: 2 m-atoms x 4 k16-steps (pre-scaled by QSCALE in projection)
    uint32_t qa[4][8];
#pragma unroll
    for (int ma = 0; ma < 2; ma++) {
        const __half* Qr0 = g_qh + base + (size_t)(qw + ma * 16 + gid) * D_MODEL;
        const __half* Qr1 = Qr0 + 8 * D_MODEL;
#pragma unroll
        for (int ks = 0; ks < 4; ks++) {
            qa[ks][ma * 4 + 0] = *(const uint32_t*)&Qr0[ks * 16 + 2 * tig];
            qa[ks][ma * 4 + 1] = *(const uint32_t*)&Qr1[ks * 16 + 2 * tig];
            qa[ks][ma * 4 + 2] = *(const uint32_t*)&Qr0[ks * 16 + 2 * tig + 8];
            qa[ks][ma * 4 + 3] = *(const uint32_t*)&Qr1[ks * 16 + 2 * tig + 8];
        }
    }

    float of[2][8][4];
#pragma unroll
    for (int ma = 0; ma < 2; ma++)
#pragma unroll
        for (int i = 0; i < 8; i++)
#pragma unroll
            for (int j = 0; j < 4; j++) of[ma][i][j] = 0.0f;
    float mm[2][2] = {{-1e30f, -1e30f}, {-1e30f, -1e30f}};
    float ll[2][2] = {{0.0f, 0.0f}, {0.0f, 0.0f}};

    // loader geometry: thread covers rows kr+16i, 16B chunk d8, for K and V
    const int kr = tid >> 3;          // 0..15
    const int d8 = tid & 7;

    const int nkb = (q0 + 128) / 64;  // 2*qt + 2 tiles of 64 keys

    // prologue: stage 0 <- tile 0
    {
        const uint4* Kt = (const uint4*)(g_kh + base) + (size_t)kr * 128 + d8;
        const uint4* Vt = (const uint4*)(g_vh + base) + (size_t)kr * 128 + d8;
        uint32_t kd = sb + kr * 144 + d8 * 16;
#pragma unroll
        for (int i = 0; i < 4; i++) {
            cpa(kd + i * 2304u, Kt + (size_t)i * 2048);          // K rows kr+16i
            cpa(kd + 9216u + i * 2304u, Vt + (size_t)i * 2048);  // V rows kr+16i
        }
        cpa_commit();
    }

    int cs = 0;                        // current stage
    for (int kb = 0; kb < nkb; kb++) {
        const int k0 = kb * 64;
        if (kb + 1 < nkb) {
            int ns = cs + 1; if (ns == 3) ns = 0;
            const uint4* Kt = (const uint4*)(g_kh + base) +
                              ((size_t)(k0 + 64 + kr)) * 128 + d8;
            const uint4* Vt = (const uint4*)(g_vh + base) +
                              ((size_t)(k0 + 64 + kr)) * 128 + d8;
            uint32_t kd = sb + ns * AST + kr * 144 + d8 * 16;
#pragma unroll
            for (int i = 0; i < 4; i++) {
                cpa(kd + i * 2304u, Kt + (size_t)i * 2048);
                cpa(kd + 9216u + i * 2304u, Vt + (size_t)i * 2048);
            }
            cpa_commit();
            cpa_wait1();
        } else {
            cpa_wait0();
        }
        __syncthreads();

        const uint32_t stg = sb + cs * AST;
#pragma unroll
        for (int h = 0; h < 2; h++) {
            const int k0h = k0 + h * 32;
            if (k0h > rowmax) break;
            const uint32_t hoff = (uint32_t)h * 4608u;

            // S = Q K^T
            float sc[2][4][4];
#pragma unroll
            for (int ma = 0; ma < 2; ma++)
#pragma unroll
                for (int nt = 0; nt < 4; nt++)
#pragma unroll
                    for (int v = 0; v < 4; v++) sc[ma][nt][v] = 0.0f;
#pragma unroll
            for (int ks = 0; ks < 4; ks++) {
                uint32_t kb0[4], kb1[4];
                ldm4(kb0, stg + k_lane + hoff + (uint32_t)ks * 32u);
                ldm4(kb1, stg + k_lane + hoff + 2304u + (uint32_t)ks * 32u);
#pragma unroll
                for (int ma = 0; ma < 2; ma++) {
                    mma_f16(sc[ma][0], qa[ks][ma*4+0], qa[ks][ma*4+1],
                            qa[ks][ma*4+2], qa[ks][ma*4+3], kb0[0], kb0[1]);
                    mma_f16(sc[ma][1], qa[ks][ma*4+0], qa[ks][ma*4+1],
                            qa[ks][ma*4+2], qa[ks][ma*4+3], kb0[2], kb0[3]);
                    mma_f16(sc[ma][2], qa[ks][ma*4+0], qa[ks][ma*4+1],
                            qa[ks][ma*4+2], qa[ks][ma*4+3], kb1[0], kb1[1]);
                    mma_f16(sc[ma][3], qa[ks][ma*4+0], qa[ks][ma*4+1],
                            qa[ks][ma*4+2], qa[ks][ma*4+3], kb1[2], kb1[3]);
                }
            }

            // causal mask
            if (k0h + 31 > qw) {
#pragma unroll
                for (int ma = 0; ma < 2; ma++) {
                    int r0g = qw + ma * 16 + gid;
                    int r1g = r0g + 8;
#pragma unroll
                    for (int nt = 0; nt < 4; nt++) {
                        int c = k0h + nt * 8 + 2 * tig;
                        if (c > r0g)     sc[ma][nt][0] = -1e30f;
                        if (c + 1 > r0g) sc[ma][nt][1] = -1e30f;
                        if (c > r1g)     sc[ma][nt][2] = -1e30f;
                        if (c + 1 > r1g) sc[ma][nt][3] = -1e30f;
                    }
                }
            }

            // online softmax (exp2 domain)
            uint32_t pa[2][2][4];
#pragma unroll
            for (int ma = 0; ma < 2; ma++) {
                float mx0 = sc[ma][0][0], mx1 = sc[ma][0][2];
#pragma unroll
                for (int nt = 0; nt < 4; nt++) {
                    mx0 = fmaxf(mx0, fmaxf(sc[ma][nt][0], sc[ma][nt][1]));
                    mx1 = fmaxf(mx1, fmaxf(sc[ma][nt][2], sc[ma][nt][3]));
                }
                mx0 = fmaxf(mx0, __shfl_xor_sync(0xffffffffu, mx0, 1));
                mx0 = fmaxf(mx0, __shfl_xor_sync(0xffffffffu, mx0, 2));
                mx1 = fmaxf(mx1, __shfl_xor_sync(0xffffffffu, mx1, 1));
                mx1 = fmaxf(mx1, __shfl_xor_sync(0xffffffffu, mx1, 2));

                float mn0 = fmaxf(mm[ma][0], mx0);
                float mn1 = fmaxf(mm[ma][1], mx1);
                float al0 = ex2(mm[ma][0] - mn0);
                float al1 = ex2(mm[ma][1] - mn1);
                mm[ma][0] = mn0; mm[ma][1] = mn1;

                float sum0 = 0.0f, sum1 = 0.0f;
#pragma unroll
                for (int nt = 0; nt < 4; nt++) {
                    sc[ma][nt][0] = ex2(sc[ma][nt][0] - mn0);
                    sc[ma][nt][1] = ex2(sc[ma][nt][1] - mn0);
                    sc[ma][nt][2] = ex2(sc[ma][nt][2] - mn1);
                    sc[ma][nt][3] = ex2(sc[ma][nt][3] - mn1);
                    sum0 += sc[ma][nt][0] + sc[ma][nt][1];
                    sum1 += sc[ma][nt][2] + sc[ma][nt][3];
                }
                sum0 += __shfl_xor_sync(0xffffffffu, sum0, 1);
                sum0 += __shfl_xor_sync(0xffffffffu, sum0, 2);
                sum1 += __shfl_xor_sync(0xffffffffu, sum1, 1);
                sum1 += __shfl_xor_sync(0xffffffffu, sum1, 2);
                ll[ma][0] = ll[ma][0] * al0 + sum0;
                ll[ma][1] = ll[ma][1] * al1 + sum1;

#pragma unroll
                for (int nt = 0; nt < 8; nt++) {
                    of[ma][nt][0] *= al0; of[ma][nt][1] *= al0;
                    of[ma][nt][2] *= al1; of[ma][nt][3] *= al1;
                }

#pragma unroll
                for (int s = 0; s < 2; s++) {
                    pa[ma][s][0] = pack2(sc[ma][2*s][0], sc[ma][2*s][1]);
                    pa[ma][s][1] = pack2(sc[ma][2*s][2], sc[ma][2*s][3]);
                    pa[ma][s][2] = pack2(sc[ma][2*s+1][0], sc[ma][2*s+1][1]);
                    pa[ma][s][3] = pack2(sc[ma][2*s+1][2], sc[ma][2*s+1][3]);
                }
            }

            // O += P @ V
#pragma unroll
            for (int s = 0; s < 2; s++) {
#pragma unroll
                for (int dp = 0; dp < 4; dp++) {
                    uint32_t vb[4];
                    ldm4t(vb, stg + v_lane + hoff + (uint32_t)s * 2304u +
                              (uint32_t)dp * 32u);
#pragma unroll
                    for (int ma = 0; ma < 2; ma++) {
                        mma_f16(of[ma][dp * 2], pa[ma][s][0], pa[ma][s][1],
                                pa[ma][s][2], pa[ma][s][3], vb[0], vb[1]);
                        mma_f16(of[ma][dp * 2 + 1], pa[ma][s][0], pa[ma][s][1],
                                pa[ma][s][2], pa[ma][s][3], vb[2], vb[3]);
                    }
                }
            }
        }
        cs++; if (cs == 3) cs = 0;
    }

    // normalize + write fp16 O
#pragma unroll
    for (int ma = 0; ma < 2; ma++) {
        float inv0 = 1.0f / ll[ma][0];
        float inv1 = 1.0f / ll[ma][1];
        __half* O0 = g_oh + base + (size_t)(qw + ma * 16 + gid) * D_MODEL;
        __half* O1 = O0 + 8 * D_MODEL;
#pragma unroll
        for (int nt = 0; nt < 8; nt++) {
            int c = nt * 8 + 2 * tig;
            *(uint32_t*)&O0[c] = pack2(of[ma][nt][0] * inv0, of[ma][nt][1] * inv0);
            *(uint32_t*)&O1[c] = pack2(of[ma][nt][2] * inv1, of[ma][nt][3] * inv1);
        }
    }
}

// ---------------------------------------------------------------------------
extern "C" void kernel_launch(void* const* d_in, const int* in_sizes, int n_in,
                              void* d_out, int out_size)
{
    const float* x  = (const float*)d_in[0];
    const float* wq = (const float*)d_in[1];
    const float* wk = (const float*)d_in[2];
    const float* wv = (const float*)d_in[3];
    const float* wo = (const float*)d_in[4];
    const int* tok  = (const int*)d_in[5];
    float* out = (float*)d_out;

    cudaFuncSetAttribute(gemm_qkv, cudaFuncAttributeMaxDynamicSharedMemorySize, GSMEM);
    cudaFuncSetAttribute(gemm_wo, cudaFuncAttributeMaxDynamicSharedMemorySize, GSMEM);
    cudaFuncSetAttribute(attn_f16, cudaFuncAttributeMaxDynamicSharedMemorySize, ASMEM);

    to_half<<<2048, 256>>>((const float4*)x, (const float4*)wq,
                           (const float4*)wk, (const float4*)wv,
                           (const float4*)wo, tok);

    dim3 gq(24, MTOT / 128);   // fused QKV
    gemm_qkv<<<gq, 128, GSMEM>>>();

    dim3 ga(SEQ / 128, BATCH * NUM_HEADS);
    attn_f16<<<ga, 128, ASMEM>>>();

    dim3 gw(D_MODEL / 128, MTOT / 128);
    gemm_wo<<<gw, 128, GSMEM>>>(out);
}